// round 13
// baseline (speedup 1.0000x reference)
#include <cuda_runtime.h>
#include <math.h>
#include <stdint.h>

#define SEQ   2048
#define HID   2048
#define NHEADS 16
#define NKVH   4
#define HDIM   128
#define NEXP   8
#define IDIM   1024
#define NSLOT (2 * SEQ)
#define ATT_SCALE 0.08838834764831845f

__device__ float g_x1[SEQ * HID];
__device__ float g_q[SEQ * NHEADS * HDIM];
__device__ float g_k[SEQ * NKVH * HDIM];
__device__ float g_v[SEQ * NKVH * HDIM];
__device__ float g_attn[SEQ * NHEADS * HDIM];
__device__ float g_x3r[SEQ * HID];
__device__ float g_moeh[NSLOT * IDIM];
__device__ float g_moeo[NSLOT * HID];
__device__ int   g_topidx[SEQ * 2];
__device__ float g_topw[SEQ * 2];
__device__ int   g_pos[SEQ * 2];
__device__ int   g_cnt[NEXP];
__device__ int   g_off[NEXP];
__device__ int   g_tok[NEXP * SEQ];

__device__ __forceinline__ uint32_t f2tf(float x) {
  uint32_t r; asm("cvt.rna.tf32.f32 %0, %1;" : "=r"(r) : "f"(x)); return r;
}
__device__ __forceinline__ float roundtf(float x) { return __uint_as_float(f2tf(x)); }

__device__ __forceinline__ void mma_tf32(float* c, const uint32_t* a, const uint32_t* b) {
  asm volatile(
      "mma.sync.aligned.m16n8k8.row.col.f32.tf32.tf32.f32 "
      "{%0,%1,%2,%3}, {%4,%5,%6,%7}, {%8,%9}, {%0,%1,%2,%3};"
      : "+f"(c[0]), "+f"(c[1]), "+f"(c[2]), "+f"(c[3])
      : "r"(a[0]), "r"(a[1]), "r"(a[2]), "r"(a[3]), "r"(b[0]), "r"(b[1]));
}
__device__ __forceinline__ void cpasync16(uint32_t dst, const float* src) {
  asm volatile("cp.async.cg.shared.global [%0], [%1], 16;\n" :: "r"(dst), "l"(src));
}
__device__ __forceinline__ void cpcommit() { asm volatile("cp.async.commit_group;\n"); }
template <int NN> __device__ __forceinline__ void cpwait() {
  asm volatile("cp.async.wait_group %0;\n" :: "n"(NN));
}

// ---------------- RMSNorm (tf32-rounded out) ----------------
__global__ void rmsnorm_kernel(const float* __restrict__ x, const float* __restrict__ w,
                               float* __restrict__ yr, int cols) {
  int row = blockIdx.x;
  const float* xr = x + (size_t)row * cols;
  float ss = 0.f;
  for (int i = threadIdx.x; i < cols; i += blockDim.x) { float v = xr[i]; ss += v * v; }
#pragma unroll
  for (int o = 16; o; o >>= 1) ss += __shfl_xor_sync(0xffffffffu, ss, o);
  __shared__ float sred[8]; __shared__ float sscale;
  if ((threadIdx.x & 31) == 0) sred[threadIdx.x >> 5] = ss;
  __syncthreads();
  if (threadIdx.x == 0) {
    float t = 0.f;
#pragma unroll
    for (int i = 0; i < 8; i++) t += sred[i];
    sscale = rsqrtf(t / (float)cols + 1e-6f);
  }
  __syncthreads();
  float sc = sscale;
  for (int i = threadIdx.x; i < cols; i += blockDim.x)
    yr[(size_t)row * cols + i] = roundtf(xr[i] * sc * w[i]);
}

// ------- fused ln2 RMSNorm + MoE gate (identical arithmetic order to the split version) --
__global__ void rmsnorm_gate(const float* __restrict__ x, const float* __restrict__ w,
                             float* __restrict__ yr, const float* __restrict__ GW,
                             const float* __restrict__ BE) {
  int row = blockIdx.x;
  const float* xr = x + (size_t)row * HID;
  float ss = 0.f;
  for (int i = threadIdx.x; i < HID; i += blockDim.x) { float v = xr[i]; ss += v * v; }
#pragma unroll
  for (int o = 16; o; o >>= 1) ss += __shfl_xor_sync(0xffffffffu, ss, o);
  __shared__ float sred[8]; __shared__ float sscale;
  if ((threadIdx.x & 31) == 0) sred[threadIdx.x >> 5] = ss;
  __syncthreads();
  if (threadIdx.x == 0) {
    float t = 0.f;
#pragma unroll
    for (int i = 0; i < 8; i++) t += sred[i];
    sscale = rsqrtf(t / (float)HID + 1e-6f);
  }
  __syncthreads();
  float sc = sscale;
  float gacc[NEXP];
#pragma unroll
  for (int e = 0; e < NEXP; e++) gacc[e] = 0.f;
  for (int i = threadIdx.x; i < HID; i += blockDim.x) {
    float v = xr[i] * sc * w[i];                    // exact (gate uses unrounded)
    yr[(size_t)row * HID + i] = roundtf(v);
    const float* g = GW + (size_t)i * NEXP;
#pragma unroll
    for (int e = 0; e < NEXP; e++) gacc[e] += v * g[e];
  }
#pragma unroll
  for (int e = 0; e < NEXP; e++)
#pragma unroll
    for (int o = 16; o; o >>= 1) gacc[e] += __shfl_xor_sync(0xffffffffu, gacc[e], o);
  __shared__ float ws[8][NEXP];
  if ((threadIdx.x & 31) == 0)
#pragma unroll
    for (int e = 0; e < NEXP; e++) ws[threadIdx.x >> 5][e] = gacc[e];
  __syncthreads();
  if (threadIdx.x == 0) {
    float scv[NEXP], bi[NEXP];
#pragma unroll
    for (int e = 0; e < NEXP; e++) {
      float lg = 0.f;
#pragma unroll
      for (int wdx = 0; wdx < 8; wdx++) lg += ws[wdx][e];
      scv[e] = 1.f / (1.f + expf(-lg));
      bi[e] = scv[e] + BE[e];
    }
    int i0 = 0;
    for (int e = 1; e < NEXP; e++) if (bi[e] > bi[i0]) i0 = e;
    int i1 = -1;
    for (int e = 0; e < NEXP; e++) {
      if (e == i0) continue;
      if (i1 < 0 || bi[e] > bi[i1]) i1 = e;
    }
    float w0 = scv[i0], w1 = scv[i1];
    float ssum = fmaxf(w0 + w1, 1e-12f);
    g_topidx[row * 2] = i0; g_topidx[row * 2 + 1] = i1;
    g_topw[row * 2] = w0 / ssum; g_topw[row * 2 + 1] = w1 / ssum;
  }
}

// ------- fused rmsnorm + partial RoPE for Q (y=0) and K (y=1), in place, tf32 out -------
__global__ void rms_rope_qk(float* __restrict__ qx, float* __restrict__ kx,
                            const float* __restrict__ qw, const float* __restrict__ kw,
                            const float* __restrict__ cp, const float* __restrict__ sp) {
  const int s = blockIdx.x;
  const int nh = (blockIdx.y == 0) ? NHEADS : NKVH;
  float* xr = ((blockIdx.y == 0) ? qx : kx) + (size_t)s * nh * HDIM;
  const float* w = (blockIdx.y == 0) ? qw : kw;
  const int cols = nh * HDIM;
  float ss = 0.f;
  for (int i = threadIdx.x; i < cols; i += blockDim.x) { float v = xr[i]; ss += v * v; }
#pragma unroll
  for (int o = 16; o; o >>= 1) ss += __shfl_xor_sync(0xffffffffu, ss, o);
  __shared__ float sred[8]; __shared__ float sscale;
  if ((threadIdx.x & 31) == 0) sred[threadIdx.x >> 5] = ss;
  __syncthreads();
  if (threadIdx.x == 0) {
    float t = 0.f;
#pragma unroll
    for (int i = 0; i < 8; i++) t += sred[i];
    sscale = rsqrtf(t / (float)cols + 1e-6f);
  }
  __syncthreads();
  float sc = sscale;
  for (int i = threadIdx.x; i < nh * 64; i += blockDim.x) {
    int h = i >> 6, sl = i & 63;
    if (sl < 32) {
      int i0 = h * HDIM + sl, i1 = i0 + 32;
      float a = xr[i0] * sc * w[i0], b = xr[i1] * sc * w[i1];
      float c = cp[s * 64 + sl], sn = sp[s * 64 + sl];
      xr[i0] = roundtf(a * c - b * sn);
      xr[i1] = roundtf(b * c + a * sn);
    } else {
      int i0 = h * HDIM + 32 + sl, i1 = i0 + 32;
      xr[i0] = roundtf(xr[i0] * sc * w[i0]);
      xr[i1] = roundtf(xr[i1] * sc * w[i1]);
    }
  }
}

// ------- tf32 GEMM, 4 warps, warp 64x64, CTA 128x128x32, 3-stage cp.async (MODE 1/4/5) --
template <int MODE>
__global__ void __launch_bounds__(128, 2)
gemm4(const float* __restrict__ A, const float* __restrict__ B,
      const float* __restrict__ D, float* __restrict__ C, int N, int K,
      const float* __restrict__ B2, const float* __restrict__ B3,
      float* __restrict__ C2, float* __restrict__ C3) {
  extern __shared__ float smem[];
  const int tid = threadIdx.x, lane = tid & 31, wid = tid >> 5;
  const int lr = lane >> 2, lc = lane & 3;
  const int wm = (wid >> 1) * 64, wn = (wid & 1) * 64;
  const int m0 = blockIdx.x * 128, by = blockIdx.y;

  const float* Bp = B; int ldb = N; int n0 = by * 128;
  if (MODE == 5) {
    if (by < 16)      { Bp = B;  ldb = 2048; n0 = by * 128; }
    else if (by < 20) { Bp = B2; ldb = 512;  n0 = (by - 16) * 128; }
    else              { Bp = B3; ldb = 512;  n0 = (by - 20) * 128; }
  }

  int e = 0, ne = 0, off = 0;
  if (MODE == 4) {
    e = blockIdx.z; ne = g_cnt[e]; off = g_off[e];
    if (m0 >= ne) return;
    Bp += (size_t)e * (size_t)K * (size_t)ldb;
  }

  uint32_t aoff[8], boff[8], Adst[8], Bdst[8];
  uint32_t sbase = (uint32_t)__cvta_generic_to_shared(smem);
#pragma unroll
  for (int i = 0; i < 8; i++) {
    int cid = tid + i * 128;
    int r = cid >> 3, kc = (cid & 7) << 2;
    int row;
    if (MODE == 4) { int mm = m0 + r; if (mm >= ne) mm = ne - 1; row = off + mm; }
    else row = m0 + r;
    aoff[i] = (uint32_t)(row * K + kc);
    Adst[i] = sbase + (uint32_t)(r * 36 + kc) * 4u;
    int bk = cid >> 5, nc = (cid & 31) << 2;
    boff[i] = (uint32_t)(bk * ldb + n0 + nc);
    Bdst[i] = sbase + (uint32_t)(3 * 128 * 36 + bk * 136 + nc) * 4u;
  }
  const uint32_t stA = 128 * 36 * 4u, stB = 32 * 136 * 4u;
  const float* As = smem;
  const float* Bs = smem + 3 * 128 * 36;

  float acc[4][8][4];
#pragma unroll
  for (int a = 0; a < 4; a++)
#pragma unroll
    for (int b = 0; b < 8; b++)
#pragma unroll
      for (int c = 0; c < 4; c++) acc[a][b][c] = 0.f;

  const int nslab = K >> 5;
  // prologue: stages 0 and 1
#pragma unroll
  for (int i = 0; i < 8; i++) {
    cpasync16(Adst[i], A + aoff[i]);
    cpasync16(Bdst[i], Bp + boff[i]);
  }
  cpcommit();
#pragma unroll
  for (int i = 0; i < 8; i++) {
    cpasync16(Adst[i] + stA, A + aoff[i] + 32);
    cpasync16(Bdst[i] + stB, Bp + boff[i] + (size_t)32 * ldb);
  }
  cpcommit();

  int st0 = 0, st2 = 2;
  for (int s = 0; s < nslab; s++) {
    if (s + 1 < nslab) cpwait<1>(); else cpwait<0>();
    __syncthreads();
    if (s + 2 < nslab) {
      int kofs = (s + 2) << 5;
#pragma unroll
      for (int i = 0; i < 8; i++) {
        cpasync16(Adst[i] + st2 * stA, A + aoff[i] + kofs);
        cpasync16(Bdst[i] + st2 * stB, Bp + boff[i] + (size_t)kofs * ldb);
      }
      cpcommit();
    }

    const float* Ab = As + st0 * (128 * 36);
    const float* Bb = Bs + st0 * (32 * 136);
#pragma unroll
    for (int ks = 0; ks < 4; ks++) {
      const int kb = ks * 8;
      uint32_t af[4][4], bf[8][2];
#pragma unroll
      for (int mt = 0; mt < 4; mt++) {
        int rb = wm + mt * 16 + lr, cc = kb + lc;
        af[mt][0] = __float_as_uint(Ab[rb * 36 + cc]);
        af[mt][1] = __float_as_uint(Ab[(rb + 8) * 36 + cc]);
        af[mt][2] = __float_as_uint(Ab[rb * 36 + cc + 4]);
        af[mt][3] = __float_as_uint(Ab[(rb + 8) * 36 + cc + 4]);
      }
#pragma unroll
      for (int nt = 0; nt < 8; nt++) {
        int cb = wn + nt * 8 + lr, rr = kb + lc;
        bf[nt][0] = f2tf(Bb[rr * 136 + cb]);
        bf[nt][1] = f2tf(Bb[(rr + 4) * 136 + cb]);
      }
#pragma unroll
      for (int mt = 0; mt < 4; mt++)
#pragma unroll
        for (int nt = 0; nt < 8; nt++) mma_tf32(acc[mt][nt], af[mt], bf[nt]);
    }
    st0 = (st0 == 2) ? 0 : st0 + 1;
    st2 = (st2 == 2) ? 0 : st2 + 1;
  }

  float* Cp = C; int ldc = N;
  if (MODE == 5) {
    if (by < 16)      { Cp = C;  ldc = 2048; }
    else if (by < 20) { Cp = C2; ldc = 512; }
    else              { Cp = C3; ldc = 512; }
  }
#pragma unroll
  for (int mt = 0; mt < 4; mt++) {
#pragma unroll
    for (int half = 0; half < 2; half++) {
      int ml = wm + mt * 16 + lr + half * 8;
      if (MODE == 1 || MODE == 5) {
        size_t rowb = (size_t)(m0 + ml) * ldc;
#pragma unroll
        for (int nt = 0; nt < 8; nt++) {
          int nn = n0 + wn + nt * 8 + 2 * lc;
          float v0 = acc[mt][nt][half * 2], v1 = acc[mt][nt][half * 2 + 1];
          if (MODE == 1) { v0 += D[rowb + nn]; v1 += D[rowb + nn + 1]; }
          if (MODE == 5 && by >= 20) { v0 = roundtf(v0); v1 = roundtf(v1); }
          Cp[rowb + nn] = v0; Cp[rowb + nn + 1] = v1;
        }
      } else {  // MODE 4
        int mm = m0 + ml;
        if (mm < ne) {
          size_t rowb = (size_t)(off + mm) * N;
#pragma unroll
          for (int nt = 0; nt < 8; nt++) {
            int nn = n0 + wn + nt * 8 + 2 * lc;
            C[rowb + nn]     = acc[mt][nt][half * 2];
            C[rowb + nn + 1] = acc[mt][nt][half * 2 + 1];
          }
        }
      }
    }
  }
}

// ------- fused MoE w1/w3: 4 warps, CTA 128x64, dual-B, 3-stage cp.async, 2 CTAs/SM -----
__global__ void __launch_bounds__(128, 2)
gemm4d(const float* __restrict__ A, const float* __restrict__ B,
       const float* __restrict__ B2, float* __restrict__ C, int N, int K) {
  extern __shared__ float smem[];
  __shared__ int toks[128];
  const int tid = threadIdx.x, lane = tid & 31, wid = tid >> 5;
  const int lr = lane >> 2, lc = lane & 3;
  const int wm = (wid >> 1) * 64, wn = (wid & 1) * 32;
  const int m0 = blockIdx.x * 128, n0 = blockIdx.y * 64;

  const int e = blockIdx.z;
  const int ne = g_cnt[e], off = g_off[e];
  if (m0 >= ne) return;
  const float* Bp  = B  + (size_t)e * (size_t)K * (size_t)N;
  const float* B2p = B2 + (size_t)e * (size_t)K * (size_t)N;
  {
    int mm = m0 + tid;
    toks[tid] = g_tok[e * SEQ + (mm < ne ? mm : ne - 1)];
  }
  __syncthreads();

  uint32_t aoff[8], boff[4], Adst[8], Bdst[4], B2dst[4];
  uint32_t sbase = (uint32_t)__cvta_generic_to_shared(smem);
#pragma unroll
  for (int i = 0; i < 8; i++) {
    int cid = tid + i * 128;
    int r = cid >> 3, kc = (cid & 7) << 2;
    aoff[i] = (uint32_t)(toks[r] * K + kc);
    Adst[i] = sbase + (uint32_t)(r * 36 + kc) * 4u;
  }
#pragma unroll
  for (int i = 0; i < 4; i++) {
    int cid = tid + i * 128;
    int bk = cid >> 4, nc = (cid & 15) << 2;
    boff[i] = (uint32_t)(bk * N + n0 + nc);
    Bdst[i]  = sbase + (uint32_t)(3 * 128 * 36 + bk * 72 + nc) * 4u;
    B2dst[i] = sbase + (uint32_t)(3 * 128 * 36 + 3 * 32 * 72 + bk * 72 + nc) * 4u;
  }
  const uint32_t stA = 128 * 36 * 4u, stB = 32 * 72 * 4u;
  const float* As  = smem;
  const float* Bs  = smem + 3 * 128 * 36;
  const float* Bs2 = smem + 3 * 128 * 36 + 3 * 32 * 72;

  float acc[4][4][4], acc2[4][4][4];
#pragma unroll
  for (int a = 0; a < 4; a++)
#pragma unroll
    for (int b = 0; b < 4; b++)
#pragma unroll
      for (int c = 0; c < 4; c++) { acc[a][b][c] = 0.f; acc2[a][b][c] = 0.f; }

  const int nslab = K >> 5;
#pragma unroll
  for (int i = 0; i < 8; i++) cpasync16(Adst[i], A + aoff[i]);
#pragma unroll
  for (int i = 0; i < 4; i++) {
    cpasync16(Bdst[i], Bp + boff[i]);
    cpasync16(B2dst[i], B2p + boff[i]);
  }
  cpcommit();
#pragma unroll
  for (int i = 0; i < 8; i++) cpasync16(Adst[i] + stA, A + aoff[i] + 32);
#pragma unroll
  for (int i = 0; i < 4; i++) {
    cpasync16(Bdst[i] + stB, Bp + boff[i] + (size_t)32 * N);
    cpasync16(B2dst[i] + stB, B2p + boff[i] + (size_t)32 * N);
  }
  cpcommit();

  int st0 = 0, st2 = 2;
  for (int s = 0; s < nslab; s++) {
    if (s + 1 < nslab) cpwait<1>(); else cpwait<0>();
    __syncthreads();
    if (s + 2 < nslab) {
      int kofs = (s + 2) << 5;
#pragma unroll
      for (int i = 0; i < 8; i++) cpasync16(Adst[i] + st2 * stA, A + aoff[i] + kofs);
#pragma unroll
      for (int i = 0; i < 4; i++) {
        cpasync16(Bdst[i] + st2 * stB, Bp + boff[i] + (size_t)kofs * N);
        cpasync16(B2dst[i] + st2 * stB, B2p + boff[i] + (size_t)kofs * N);
      }
      cpcommit();
    }

    const float* Ab  = As  + st0 * (128 * 36);
    const float* Bb  = Bs  + st0 * (32 * 72);
    const float* Bb2 = Bs2 + st0 * (32 * 72);
#pragma unroll
    for (int ks = 0; ks < 4; ks++) {
      const int kb = ks * 8;
      uint32_t af[4][4], bf[4][2], bf2[4][2];
#pragma unroll
      for (int mt = 0; mt < 4; mt++) {
        int rb = wm + mt * 16 + lr, cc = kb + lc;
        af[mt][0] = __float_as_uint(Ab[rb * 36 + cc]);
        af[mt][1] = __float_as_uint(Ab[(rb + 8) * 36 + cc]);
        af[mt][2] = __float_as_uint(Ab[rb * 36 + cc + 4]);
        af[mt][3] = __float_as_uint(Ab[(rb + 8) * 36 + cc + 4]);
      }
#pragma unroll
      for (int nt = 0; nt < 4; nt++) {
        int cb = wn + nt * 8 + lr, rr = kb + lc;
        bf[nt][0]  = f2tf(Bb[rr * 72 + cb]);
        bf[nt][1]  = f2tf(Bb[(rr + 4) * 72 + cb]);
        bf2[nt][0] = f2tf(Bb2[rr * 72 + cb]);
        bf2[nt][1] = f2tf(Bb2[(rr + 4) * 72 + cb]);
      }
#pragma unroll
      for (int mt = 0; mt < 4; mt++)
#pragma unroll
        for (int nt = 0; nt < 4; nt++) {
          mma_tf32(acc[mt][nt], af[mt], bf[nt]);
          mma_tf32(acc2[mt][nt], af[mt], bf2[nt]);
        }
    }
    st0 = (st0 == 2) ? 0 : st0 + 1;
    st2 = (st2 == 2) ? 0 : st2 + 1;
  }

#pragma unroll
  for (int mt = 0; mt < 4; mt++) {
#pragma unroll
    for (int half = 0; half < 2; half++) {
      int ml = wm + mt * 16 + lr + half * 8;
      int mm = m0 + ml;
      if (mm < ne) {
        size_t rowb = (size_t)(off + mm) * N;
#pragma unroll
        for (int nt = 0; nt < 4; nt++) {
          int nn = n0 + wn + nt * 8 + 2 * lc;
          float g0 = acc[mt][nt][half * 2], g1 = acc[mt][nt][half * 2 + 1];
          C[rowb + nn]     = roundtf(g0 * acc2[mt][nt][half * 2] / (1.f + __expf(-g0)));
          C[rowb + nn + 1] = roundtf(g1 * acc2[mt][nt][half * 2 + 1] / (1.f + __expf(-g1)));
        }
      }
    }
  }
}

// ------- causal flash attention (champion): tf32 mma, Q-frags in regs, 2 CTAs/SM -------
__global__ void __launch_bounds__(128, 2) flash_tc(const float* __restrict__ Q,
                                                   const float* __restrict__ Kp,
                                                   const float* __restrict__ Vp,
                                                   float* __restrict__ O) {
  extern __shared__ float sm[];
  float* Ks = sm;
  float* Vs = sm + 64 * 132;
  const int qt = gridDim.x - 1 - blockIdx.x;
  const int head = blockIdx.y, kh = head >> 2;
  const int tid = threadIdx.x, lane = tid & 31, w = tid >> 5;
  const int q0 = qt * 64, lr = lane >> 2, lc = lane & 3;
  const int rloc = w * 16 + lr;
  const int gr0 = q0 + rloc, gr1 = gr0 + 8;

  for (int i = tid; i < 64 * 32; i += 128) {
    int r = i >> 5, c4 = (i & 31) << 2;
    *(float4*)&Ks[r * 132 + c4] = *(const float4*)&Q[(size_t)(q0 + r) * 2048 + head * HDIM + c4];
  }
  __syncthreads();
  uint32_t qf[16][4];
#pragma unroll
  for (int ks = 0; ks < 16; ks++) {
    const int kb = ks * 8;
    qf[ks][0] = __float_as_uint(Ks[rloc * 132 + kb + lc]);
    qf[ks][1] = __float_as_uint(Ks[(rloc + 8) * 132 + kb + lc]);
    qf[ks][2] = __float_as_uint(Ks[rloc * 132 + kb + lc + 4]);
    qf[ks][3] = __float_as_uint(Ks[(rloc + 8) * 132 + kb + lc + 4]);
  }

  float mr0 = -3.0e38f, mr1 = -3.0e38f, li0 = 0.f, li1 = 0.f;
  float oacc[16][4];
#pragma unroll
  for (int i = 0; i < 16; i++)
#pragma unroll
    for (int j = 0; j < 4; j++) oacc[i][j] = 0.f;

  for (int kt = 0; kt <= qt; kt++) {
    __syncthreads();
    for (int i = tid; i < 64 * 32; i += 128) {
      int r = i >> 5, c4 = (i & 31) << 2;
      size_t gb = (size_t)(kt * 64 + r) * 512 + kh * HDIM + c4;
      *(float4*)&Ks[r * 132 + c4] = *(const float4*)&Kp[gb];
      *(float4*)&Vs[r * 132 + c4] = *(const float4*)&Vp[gb];
    }
    __syncthreads();

    float sacc[8][4];
#pragma unroll
    for (int i = 0; i < 8; i++)
#pragma unroll
      for (int j = 0; j < 4; j++) sacc[i][j] = 0.f;
#pragma unroll
    for (int ks = 0; ks < 16; ks++) {
      const int kb = ks * 8;
#pragma unroll
      for (int nt = 0; nt < 8; nt++) {
        int cb = nt * 8 + lr;
        uint32_t b[2];
        b[0] = __float_as_uint(Ks[cb * 132 + kb + lc]);
        b[1] = __float_as_uint(Ks[cb * 132 + kb + lc + 4]);
        mma_tf32(sacc[nt], qf[ks], b);
      }
    }

    const bool diag = (kt == qt);
#pragma unroll
    for (int nt = 0; nt < 8; nt++) {
      int gc = kt * 64 + nt * 8 + 2 * lc;
#pragma unroll
      for (int j = 0; j < 4; j++) {
        float v = sacc[nt][j] * ATT_SCALE;
        if (diag && (gc + (j & 1)) > ((j < 2) ? gr0 : gr1)) v = -1.0e30f;
        sacc[nt][j] = v;
      }
    }

    float mx0 = -3.0e38f, mx1 = -3.0e38f;
#pragma unroll
    for (int nt = 0; nt < 8; nt++) {
      mx0 = fmaxf(mx0, fmaxf(sacc[nt][0], sacc[nt][1]));
      mx1 = fmaxf(mx1, fmaxf(sacc[nt][2], sacc[nt][3]));
    }
    mx0 = fmaxf(mx0, __shfl_xor_sync(0xffffffffu, mx0, 1));
    mx0 = fmaxf(mx0, __shfl_xor_sync(0xffffffffu, mx0, 2));
    mx1 = fmaxf(mx1, __shfl_xor_sync(0xffffffffu, mx1, 1));
    mx1 = fmaxf(mx1, __shfl_xor_sync(0xffffffffu, mx1, 2));
    float mn0 = fmaxf(mr0, mx0), mn1 = fmaxf(mr1, mx1);
    float co0 = __expf(mr0 - mn0), co1 = __expf(mr1 - mn1);
    mr0 = mn0; mr1 = mn1;
    float rs0 = 0.f, rs1 = 0.f;
#pragma unroll
    for (int nt = 0; nt < 8; nt++) {
      sacc[nt][0] = __expf(sacc[nt][0] - mn0);
      sacc[nt][1] = __expf(sacc[nt][1] - mn0);
      sacc[nt][2] = __expf(sacc[nt][2] - mn1);
      sacc[nt][3] = __expf(sacc[nt][3] - mn1);
      rs0 += sacc[nt][0] + sacc[nt][1];
      rs1 += sacc[nt][2] + sacc[nt][3];
    }
    rs0 += __shfl_xor_sync(0xffffffffu, rs0, 1);
    rs0 += __shfl_xor_sync(0xffffffffu, rs0, 2);
    rs1 += __shfl_xor_sync(0xffffffffu, rs1, 1);
    rs1 += __shfl_xor_sync(0xffffffffu, rs1, 2);
    li0 = li0 * co0 + rs0; li1 = li1 * co1 + rs1;
#pragma unroll
    for (int i = 0; i < 16; i++) {
      oacc[i][0] *= co0; oacc[i][1] *= co0;
      oacc[i][2] *= co1; oacc[i][3] *= co1;
    }

#pragma unroll
    for (int kc = 0; kc < 8; kc++) {
      int src0 = (lane & ~3) | (lc >> 1), src1 = src0 + 2;
      float v00 = __shfl_sync(0xffffffffu, sacc[kc][0], src0);
      float v01 = __shfl_sync(0xffffffffu, sacc[kc][1], src0);
      float v10 = __shfl_sync(0xffffffffu, sacc[kc][0], src1);
      float v11 = __shfl_sync(0xffffffffu, sacc[kc][1], src1);
      float w00 = __shfl_sync(0xffffffffu, sacc[kc][2], src0);
      float w01 = __shfl_sync(0xffffffffu, sacc[kc][3], src0);
      float w10 = __shfl_sync(0xffffffffu, sacc[kc][2], src1);
      float w11 = __shfl_sync(0xffffffffu, sacc[kc][3], src1);
      uint32_t a[4];
      a[0] = f2tf((lc & 1) ? v01 : v00);
      a[1] = f2tf((lc & 1) ? w01 : w00);
      a[2] = f2tf((lc & 1) ? v11 : v10);
      a[3] = f2tf((lc & 1) ? w11 : w10);
      const int kb = kc * 8;
#pragma unroll
      for (int nt = 0; nt < 16; nt++) {
        int cb = nt * 8 + lr;
        uint32_t b[2];
        b[0] = __float_as_uint(Vs[(kb + lc) * 132 + cb]);
        b[1] = __float_as_uint(Vs[(kb + lc + 4) * 132 + cb]);
        mma_tf32(oacc[nt], a, b);
      }
    }
  }

  float inv0 = 1.f / li0, inv1 = 1.f / li1;
  size_t r0b = (size_t)gr0 * 2048 + head * HDIM, r1b = (size_t)gr1 * 2048 + head * HDIM;
#pragma unroll
  for (int nt = 0; nt < 16; nt++) {
    int nn = nt * 8 + 2 * lc;
    O[r0b + nn]     = roundtf(oacc[nt][0] * inv0);
    O[r0b + nn + 1] = roundtf(oacc[nt][1] * inv0);
    O[r1b + nn]     = roundtf(oacc[nt][2] * inv1);
    O[r1b + nn + 1] = roundtf(oacc[nt][3] * inv1);
  }
}

// ---------------- routing ----------------
__global__ void routing_kernel() {
  __shared__ int scnt[NEXP];
  int tid = threadIdx.x;
  if (tid < NEXP) scnt[tid] = 0;
  __syncthreads();
  for (int s = tid; s < SEQ * 2; s += blockDim.x) {
    int e = g_topidx[s];
    int p = atomicAdd(&scnt[e], 1);
    g_pos[s] = p;
    g_tok[e * SEQ + p] = s >> 1;
  }
  __syncthreads();
  if (tid == 0) {
    int acc = 0;
    for (int e = 0; e < NEXP; e++) {
      g_off[e] = acc; g_cnt[e] = scnt[e]; acc += scnt[e];
    }
  }
}

// ---------------- MoE combine (float4) ----------------
__global__ void combine_kernel(float* __restrict__ out, const float* __restrict__ moeo) {
  int t = blockIdx.x;
  int s0 = g_off[g_topidx[t * 2]] + g_pos[t * 2];
  int s1 = g_off[g_topidx[t * 2 + 1]] + g_pos[t * 2 + 1];
  float w0 = g_topw[t * 2], w1 = g_topw[t * 2 + 1];
  const float4* r0 = (const float4*)(moeo + (size_t)s0 * HID);
  const float4* r1 = (const float4*)(moeo + (size_t)s1 * HID);
  float4* o = (float4*)(out + (size_t)t * HID);
  for (int i = threadIdx.x; i < HID / 4; i += blockDim.x) {
    float4 a = r0[i], b = r1[i], c = o[i];
    c.x += w0 * a.x + w1 * b.x;
    c.y += w0 * a.y + w1 * b.y;
    c.z += w0 * a.z + w1 * b.z;
    c.w += w0 * a.w + w1 * b.w;
    o[i] = c;
  }
}

// ---------------- launch ----------------
extern "C" void kernel_launch(void* const* d_in, const int* in_sizes, int n_in,
                              void* d_out, int out_size) {
  const float* hidden = (const float*)d_in[0];
  const float* cosp = (const float*)d_in[2];
  const float* sinp = (const float*)d_in[3];
  const float* ln1  = (const float*)d_in[4];
  const float* ln2  = (const float*)d_in[5];
  const float* wq   = (const float*)d_in[6];
  const float* wk   = (const float*)d_in[7];
  const float* wv   = (const float*)d_in[8];
  const float* wo   = (const float*)d_in[9];
  const float* qn   = (const float*)d_in[10];
  const float* kn   = (const float*)d_in[11];
  const float* gw   = (const float*)d_in[12];
  const float* be   = (const float*)d_in[13];
  const float* w1   = (const float*)d_in[14];
  const float* w3   = (const float*)d_in[15];
  const float* w2   = (const float*)d_in[16];
  float* out = (float*)d_out;

  float *x1, *q, *k, *v, *attn, *x3r, *moeh, *moeo;
  cudaGetSymbolAddress((void**)&x1, g_x1);
  cudaGetSymbolAddress((void**)&q, g_q);
  cudaGetSymbolAddress((void**)&k, g_k);
  cudaGetSymbolAddress((void**)&v, g_v);
  cudaGetSymbolAddress((void**)&attn, g_attn);
  cudaGetSymbolAddress((void**)&x3r, g_x3r);
  cudaGetSymbolAddress((void**)&moeh, g_moeh);
  cudaGetSymbolAddress((void**)&moeo, g_moeo);

  const int GS3   = (3 * 128 * 36 + 3 * 32 * 136) * 4;  // 107520 B (2 CTAs/SM)
  const int GS4D3 = (3 * 128 * 36 + 6 * 32 * 72) * 4;   // 110592 B (2 CTAs/SM)
  cudaFuncSetAttribute(gemm4<1>, cudaFuncAttributeMaxDynamicSharedMemorySize, GS3);
  cudaFuncSetAttribute(gemm4<4>, cudaFuncAttributeMaxDynamicSharedMemorySize, GS3);
  cudaFuncSetAttribute(gemm4<5>, cudaFuncAttributeMaxDynamicSharedMemorySize, GS3);
  cudaFuncSetAttribute(gemm4d, cudaFuncAttributeMaxDynamicSharedMemorySize, GS4D3);
  const int FS = 2 * 64 * 132 * 4;                      // 67584 B -> 2 CTAs/SM
  cudaFuncSetAttribute(flash_tc, cudaFuncAttributeMaxDynamicSharedMemorySize, FS);

  rmsnorm_kernel<<<SEQ, 256>>>(hidden, ln1, x1, HID);                         // #1
  gemm4<5><<<dim3(16, 24), 128, GS3>>>(x1, wq, nullptr, q, 2048, 2048, wk, wv, k, v); // #2
  rms_rope_qk<<<dim3(SEQ, 2), 256>>>(q, k, qn, kn, cosp, sinp);               // #3
  flash_tc<<<dim3(32, NHEADS), 128, FS>>>(q, k, v, attn);                     // #4 <- profiled
  gemm4<1><<<dim3(16, 16), 128, GS3>>>(attn, wo, hidden, out, 2048, 2048,
                                       nullptr, nullptr, nullptr, nullptr);
  rmsnorm_gate<<<SEQ, 256>>>(out, ln2, x3r, gw, be);
  routing_kernel<<<1, 256>>>();
  gemm4d<<<dim3(16, 16, 8), 128, GS4D3>>>(x3r, w1, w3, moeh, IDIM, HID);
  gemm4<4><<<dim3(16, 16, 8), 128, GS3>>>(moeh, w2, nullptr, moeo, HID, IDIM,
                                          nullptr, nullptr, nullptr, nullptr);
  combine_kernel<<<SEQ, 256>>>(out, moeo);
}

// round 14
// speedup vs baseline: 1.0224x; 1.0224x over previous
#include <cuda_runtime.h>
#include <math.h>
#include <stdint.h>

#define SEQ   2048
#define HID   2048
#define NHEADS 16
#define NKVH   4
#define HDIM   128
#define NEXP   8
#define IDIM   1024
#define NSLOT (2 * SEQ)
#define ATT_SCALE 0.08838834764831845f

__device__ float g_x1[SEQ * HID];
__device__ float g_q[SEQ * NHEADS * HDIM];
__device__ float g_k[SEQ * NKVH * HDIM];
__device__ float g_v[SEQ * NKVH * HDIM];
__device__ float g_attn[SEQ * NHEADS * HDIM];
__device__ float g_x3r[SEQ * HID];
__device__ float g_moeh[NSLOT * IDIM];
__device__ float g_moeo[NSLOT * HID];
__device__ int   g_topidx[SEQ * 2];
__device__ float g_topw[SEQ * 2];
__device__ int   g_pos[SEQ * 2];
__device__ int   g_cnt[NEXP];
__device__ int   g_off[NEXP];
__device__ int   g_tok[NEXP * SEQ];

__device__ __forceinline__ uint32_t f2tf(float x) {
  uint32_t r; asm("cvt.rna.tf32.f32 %0, %1;" : "=r"(r) : "f"(x)); return r;
}
__device__ __forceinline__ float roundtf(float x) { return __uint_as_float(f2tf(x)); }

__device__ __forceinline__ void mma_tf32(float* c, const uint32_t* a, const uint32_t* b) {
  asm volatile(
      "mma.sync.aligned.m16n8k8.row.col.f32.tf32.tf32.f32 "
      "{%0,%1,%2,%3}, {%4,%5,%6,%7}, {%8,%9}, {%0,%1,%2,%3};"
      : "+f"(c[0]), "+f"(c[1]), "+f"(c[2]), "+f"(c[3])
      : "r"(a[0]), "r"(a[1]), "r"(a[2]), "r"(a[3]), "r"(b[0]), "r"(b[1]));
}
__device__ __forceinline__ void cpasync16(uint32_t dst, const float* src) {
  asm volatile("cp.async.cg.shared.global [%0], [%1], 16;\n" :: "r"(dst), "l"(src));
}
__device__ __forceinline__ void cpcommit() { asm volatile("cp.async.commit_group;\n"); }
template <int NN> __device__ __forceinline__ void cpwait() {
  asm volatile("cp.async.wait_group %0;\n" :: "n"(NN));
}

// ---------------- RMSNorm (tf32-rounded out) ----------------
__global__ void rmsnorm_kernel(const float* __restrict__ x, const float* __restrict__ w,
                               float* __restrict__ yr, int cols) {
  int row = blockIdx.x;
  const float* xr = x + (size_t)row * cols;
  float ss = 0.f;
  for (int i = threadIdx.x; i < cols; i += blockDim.x) { float v = xr[i]; ss += v * v; }
#pragma unroll
  for (int o = 16; o; o >>= 1) ss += __shfl_xor_sync(0xffffffffu, ss, o);
  __shared__ float sred[8]; __shared__ float sscale;
  if ((threadIdx.x & 31) == 0) sred[threadIdx.x >> 5] = ss;
  __syncthreads();
  if (threadIdx.x == 0) {
    float t = 0.f;
#pragma unroll
    for (int i = 0; i < 8; i++) t += sred[i];
    sscale = rsqrtf(t / (float)cols + 1e-6f);
  }
  __syncthreads();
  float sc = sscale;
  for (int i = threadIdx.x; i < cols; i += blockDim.x)
    yr[(size_t)row * cols + i] = roundtf(xr[i] * sc * w[i]);
}

// ------- fused ln2 RMSNorm + MoE gate (identical arithmetic order to split version) -----
__global__ void rmsnorm_gate(const float* __restrict__ x, const float* __restrict__ w,
                             float* __restrict__ yr, const float* __restrict__ GW,
                             const float* __restrict__ BE) {
  int row = blockIdx.x;
  const float* xr = x + (size_t)row * HID;
  float ss = 0.f;
  for (int i = threadIdx.x; i < HID; i += blockDim.x) { float v = xr[i]; ss += v * v; }
#pragma unroll
  for (int o = 16; o; o >>= 1) ss += __shfl_xor_sync(0xffffffffu, ss, o);
  __shared__ float sred[8]; __shared__ float sscale;
  if ((threadIdx.x & 31) == 0) sred[threadIdx.x >> 5] = ss;
  __syncthreads();
  if (threadIdx.x == 0) {
    float t = 0.f;
#pragma unroll
    for (int i = 0; i < 8; i++) t += sred[i];
    sscale = rsqrtf(t / (float)HID + 1e-6f);
  }
  __syncthreads();
  float sc = sscale;
  float gacc[NEXP];
#pragma unroll
  for (int e = 0; e < NEXP; e++) gacc[e] = 0.f;
  for (int i = threadIdx.x; i < HID; i += blockDim.x) {
    float v = xr[i] * sc * w[i];                    // exact (gate uses unrounded)
    yr[(size_t)row * HID + i] = roundtf(v);
    const float* g = GW + (size_t)i * NEXP;
#pragma unroll
    for (int e = 0; e < NEXP; e++) gacc[e] += v * g[e];
  }
#pragma unroll
  for (int e = 0; e < NEXP; e++)
#pragma unroll
    for (int o = 16; o; o >>= 1) gacc[e] += __shfl_xor_sync(0xffffffffu, gacc[e], o);
  __shared__ float ws[8][NEXP];
  if ((threadIdx.x & 31) == 0)
#pragma unroll
    for (int e = 0; e < NEXP; e++) ws[threadIdx.x >> 5][e] = gacc[e];
  __syncthreads();
  if (threadIdx.x == 0) {
    float scv[NEXP], bi[NEXP];
#pragma unroll
    for (int e = 0; e < NEXP; e++) {
      float lg = 0.f;
#pragma unroll
      for (int wdx = 0; wdx < 8; wdx++) lg += ws[wdx][e];
      scv[e] = 1.f / (1.f + expf(-lg));
      bi[e] = scv[e] + BE[e];
    }
    int i0 = 0;
    for (int e = 1; e < NEXP; e++) if (bi[e] > bi[i0]) i0 = e;
    int i1 = -1;
    for (int e = 0; e < NEXP; e++) {
      if (e == i0) continue;
      if (i1 < 0 || bi[e] > bi[i1]) i1 = e;
    }
    float w0 = scv[i0], w1 = scv[i1];
    float ssum = fmaxf(w0 + w1, 1e-12f);
    g_topidx[row * 2] = i0; g_topidx[row * 2 + 1] = i1;
    g_topw[row * 2] = w0 / ssum; g_topw[row * 2 + 1] = w1 / ssum;
  }
}

// ------- fused rmsnorm + partial RoPE for Q (y=0) and K (y=1), in place, tf32 out -------
__global__ void rms_rope_qk(float* __restrict__ qx, float* __restrict__ kx,
                            const float* __restrict__ qw, const float* __restrict__ kw,
                            const float* __restrict__ cp, const float* __restrict__ sp) {
  const int s = blockIdx.x;
  const int nh = (blockIdx.y == 0) ? NHEADS : NKVH;
  float* xr = ((blockIdx.y == 0) ? qx : kx) + (size_t)s * nh * HDIM;
  const float* w = (blockIdx.y == 0) ? qw : kw;
  const int cols = nh * HDIM;
  float ss = 0.f;
  for (int i = threadIdx.x; i < cols; i += blockDim.x) { float v = xr[i]; ss += v * v; }
#pragma unroll
  for (int o = 16; o; o >>= 1) ss += __shfl_xor_sync(0xffffffffu, ss, o);
  __shared__ float sred[8]; __shared__ float sscale;
  if ((threadIdx.x & 31) == 0) sred[threadIdx.x >> 5] = ss;
  __syncthreads();
  if (threadIdx.x == 0) {
    float t = 0.f;
#pragma unroll
    for (int i = 0; i < 8; i++) t += sred[i];
    sscale = rsqrtf(t / (float)cols + 1e-6f);
  }
  __syncthreads();
  float sc = sscale;
  for (int i = threadIdx.x; i < nh * 64; i += blockDim.x) {
    int h = i >> 6, sl = i & 63;
    if (sl < 32) {
      int i0 = h * HDIM + sl, i1 = i0 + 32;
      float a = xr[i0] * sc * w[i0], b = xr[i1] * sc * w[i1];
      float c = cp[s * 64 + sl], sn = sp[s * 64 + sl];
      xr[i0] = roundtf(a * c - b * sn);
      xr[i1] = roundtf(b * c + a * sn);
    } else {
      int i0 = h * HDIM + 32 + sl, i1 = i0 + 32;
      xr[i0] = roundtf(xr[i0] * sc * w[i0]);
      xr[i1] = roundtf(xr[i1] * sc * w[i1]);
    }
  }
}

// ------- tf32 GEMM (r12 champion): 4 warps, warp 64x64, CTA 128x128x32, 2-stage --------
template <int MODE>
__global__ void __launch_bounds__(128, 2)
gemm4(const float* __restrict__ A, const float* __restrict__ B,
      const float* __restrict__ D, float* __restrict__ C, int N, int K,
      const float* __restrict__ B2, const float* __restrict__ B3,
      float* __restrict__ C2, float* __restrict__ C3) {
  extern __shared__ float smem[];
  const int tid = threadIdx.x, lane = tid & 31, wid = tid >> 5;
  const int lr = lane >> 2, lc = lane & 3;
  const int wm = (wid >> 1) * 64, wn = (wid & 1) * 64;
  const int m0 = blockIdx.x * 128, by = blockIdx.y;

  const float* Bp = B; int ldb = N; int n0 = by * 128;
  if (MODE == 5) {
    if (by < 16)      { Bp = B;  ldb = 2048; n0 = by * 128; }
    else if (by < 20) { Bp = B2; ldb = 512;  n0 = (by - 16) * 128; }
    else              { Bp = B3; ldb = 512;  n0 = (by - 20) * 128; }
  }

  int e = 0, ne = 0, off = 0;
  if (MODE == 4) {
    e = blockIdx.z; ne = g_cnt[e]; off = g_off[e];
    if (m0 >= ne) return;
    Bp += (size_t)e * (size_t)K * (size_t)ldb;
  }

  uint32_t aoff[8], boff[8], Adst[8], Bdst[8];
  uint32_t sbase = (uint32_t)__cvta_generic_to_shared(smem);
#pragma unroll
  for (int i = 0; i < 8; i++) {
    int cid = tid + i * 128;
    int r = cid >> 3, kc = (cid & 7) << 2;
    int row;
    if (MODE == 4) { int mm = m0 + r; if (mm >= ne) mm = ne - 1; row = off + mm; }
    else row = m0 + r;
    aoff[i] = (uint32_t)(row * K + kc);
    Adst[i] = sbase + (uint32_t)(r * 36 + kc) * 4u;
    int bk = cid >> 5, nc = (cid & 31) << 2;
    boff[i] = (uint32_t)(bk * ldb + n0 + nc);
    Bdst[i] = sbase + (uint32_t)(2 * 128 * 36 + bk * 136 + nc) * 4u;
  }
  const uint32_t stA = 128 * 36 * 4u, stB = 32 * 136 * 4u;
  const float* As = smem;
  const float* Bs = smem + 2 * 128 * 36;

  float acc[4][8][4];
#pragma unroll
  for (int a = 0; a < 4; a++)
#pragma unroll
    for (int b = 0; b < 8; b++)
#pragma unroll
      for (int c = 0; c < 4; c++) acc[a][b][c] = 0.f;

  const int nslab = K >> 5;
#pragma unroll
  for (int i = 0; i < 8; i++) {
    cpasync16(Adst[i], A + aoff[i]);
    cpasync16(Bdst[i], Bp + boff[i]);
  }
  cpcommit();

  for (int s = 0; s < nslab; s++) {
    if (s + 1 < nslab) {
      int kofs = (s + 1) << 5;
      uint32_t so = ((s + 1) & 1) ? 1u : 0u;
#pragma unroll
      for (int i = 0; i < 8; i++) {
        cpasync16(Adst[i] + so * stA, A + aoff[i] + kofs);
        cpasync16(Bdst[i] + so * stB, Bp + boff[i] + (size_t)kofs * ldb);
      }
      cpcommit();
      cpwait<1>();
    } else cpwait<0>();
    __syncthreads();

    const float* Ab = As + (s & 1) * (128 * 36);
    const float* Bb = Bs + (s & 1) * (32 * 136);
#pragma unroll
    for (int ks = 0; ks < 4; ks++) {
      const int kb = ks * 8;
      uint32_t af[4][4], bf[8][2];
#pragma unroll
      for (int mt = 0; mt < 4; mt++) {
        int rb = wm + mt * 16 + lr, cc = kb + lc;
        af[mt][0] = __float_as_uint(Ab[rb * 36 + cc]);
        af[mt][1] = __float_as_uint(Ab[(rb + 8) * 36 + cc]);
        af[mt][2] = __float_as_uint(Ab[rb * 36 + cc + 4]);
        af[mt][3] = __float_as_uint(Ab[(rb + 8) * 36 + cc + 4]);
      }
#pragma unroll
      for (int nt = 0; nt < 8; nt++) {
        int cb = wn + nt * 8 + lr, rr = kb + lc;
        bf[nt][0] = f2tf(Bb[rr * 136 + cb]);
        bf[nt][1] = f2tf(Bb[(rr + 4) * 136 + cb]);
      }
#pragma unroll
      for (int mt = 0; mt < 4; mt++)
#pragma unroll
        for (int nt = 0; nt < 8; nt++) mma_tf32(acc[mt][nt], af[mt], bf[nt]);
    }
    __syncthreads();
  }

  float* Cp = C; int ldc = N;
  if (MODE == 5) {
    if (by < 16)      { Cp = C;  ldc = 2048; }
    else if (by < 20) { Cp = C2; ldc = 512; }
    else              { Cp = C3; ldc = 512; }
  }
#pragma unroll
  for (int mt = 0; mt < 4; mt++) {
#pragma unroll
    for (int half = 0; half < 2; half++) {
      int ml = wm + mt * 16 + lr + half * 8;
      if (MODE == 1 || MODE == 5) {
        size_t rowb = (size_t)(m0 + ml) * ldc;
#pragma unroll
        for (int nt = 0; nt < 8; nt++) {
          int nn = n0 + wn + nt * 8 + 2 * lc;
          float v0 = acc[mt][nt][half * 2], v1 = acc[mt][nt][half * 2 + 1];
          if (MODE == 1) { v0 += D[rowb + nn]; v1 += D[rowb + nn + 1]; }
          if (MODE == 5 && by >= 20) { v0 = roundtf(v0); v1 = roundtf(v1); }
          Cp[rowb + nn] = v0; Cp[rowb + nn + 1] = v1;
        }
      } else {  // MODE 4
        int mm = m0 + ml;
        if (mm < ne) {
          size_t rowb = (size_t)(off + mm) * N;
#pragma unroll
          for (int nt = 0; nt < 8; nt++) {
            int nn = n0 + wn + nt * 8 + 2 * lc;
            C[rowb + nn]     = acc[mt][nt][half * 2];
            C[rowb + nn + 1] = acc[mt][nt][half * 2 + 1];
          }
        }
      }
    }
  }
}

// ------- fused MoE w1/w3 (r12 champion): 4 warps, CTA 128x64, dual-B, 2-stage ----------
__global__ void __launch_bounds__(128, 2)
gemm4d(const float* __restrict__ A, const float* __restrict__ B,
       const float* __restrict__ B2, float* __restrict__ C, int N, int K) {
  extern __shared__ float smem[];
  __shared__ int toks[128];
  const int tid = threadIdx.x, lane = tid & 31, wid = tid >> 5;
  const int lr = lane >> 2, lc = lane & 3;
  const int wm = (wid >> 1) * 64, wn = (wid & 1) * 32;
  const int m0 = blockIdx.x * 128, n0 = blockIdx.y * 64;

  const int e = blockIdx.z;
  const int ne = g_cnt[e], off = g_off[e];
  if (m0 >= ne) return;
  const float* Bp  = B  + (size_t)e * (size_t)K * (size_t)N;
  const float* B2p = B2 + (size_t)e * (size_t)K * (size_t)N;
  {
    int mm = m0 + tid;
    toks[tid] = g_tok[e * SEQ + (mm < ne ? mm : ne - 1)];
  }
  __syncthreads();

  uint32_t aoff[8], boff[4], Adst[8], Bdst[4], B2dst[4];
  uint32_t sbase = (uint32_t)__cvta_generic_to_shared(smem);
#pragma unroll
  for (int i = 0; i < 8; i++) {
    int cid = tid + i * 128;
    int r = cid >> 3, kc = (cid & 7) << 2;
    aoff[i] = (uint32_t)(toks[r] * K + kc);
    Adst[i] = sbase + (uint32_t)(r * 36 + kc) * 4u;
  }
#pragma unroll
  for (int i = 0; i < 4; i++) {
    int cid = tid + i * 128;
    int bk = cid >> 4, nc = (cid & 15) << 2;
    boff[i] = (uint32_t)(bk * N + n0 + nc);
    Bdst[i]  = sbase + (uint32_t)(2 * 128 * 36 + bk * 72 + nc) * 4u;
    B2dst[i] = sbase + (uint32_t)(2 * 128 * 36 + 2 * 32 * 72 + bk * 72 + nc) * 4u;
  }
  const uint32_t stA = 128 * 36 * 4u, stB = 32 * 72 * 4u;
  const float* As  = smem;
  const float* Bs  = smem + 2 * 128 * 36;
  const float* Bs2 = smem + 2 * 128 * 36 + 2 * 32 * 72;

  float acc[4][4][4], acc2[4][4][4];
#pragma unroll
  for (int a = 0; a < 4; a++)
#pragma unroll
    for (int b = 0; b < 4; b++)
#pragma unroll
      for (int c = 0; c < 4; c++) { acc[a][b][c] = 0.f; acc2[a][b][c] = 0.f; }

  const int nslab = K >> 5;
#pragma unroll
  for (int i = 0; i < 8; i++) cpasync16(Adst[i], A + aoff[i]);
#pragma unroll
  for (int i = 0; i < 4; i++) {
    cpasync16(Bdst[i], Bp + boff[i]);
    cpasync16(B2dst[i], B2p + boff[i]);
  }
  cpcommit();

  for (int s = 0; s < nslab; s++) {
    if (s + 1 < nslab) {
      int kofs = (s + 1) << 5;
      uint32_t so = ((s + 1) & 1) ? 1u : 0u;
#pragma unroll
      for (int i = 0; i < 8; i++) cpasync16(Adst[i] + so * stA, A + aoff[i] + kofs);
#pragma unroll
      for (int i = 0; i < 4; i++) {
        cpasync16(Bdst[i] + so * stB, Bp + boff[i] + (size_t)kofs * N);
        cpasync16(B2dst[i] + so * stB, B2p + boff[i] + (size_t)kofs * N);
      }
      cpcommit();
      cpwait<1>();
    } else cpwait<0>();
    __syncthreads();

    const float* Ab  = As  + (s & 1) * (128 * 36);
    const float* Bb  = Bs  + (s & 1) * (32 * 72);
    const float* Bb2 = Bs2 + (s & 1) * (32 * 72);
#pragma unroll
    for (int ks = 0; ks < 4; ks++) {
      const int kb = ks * 8;
      uint32_t af[4][4], bf[4][2], bf2[4][2];
#pragma unroll
      for (int mt = 0; mt < 4; mt++) {
        int rb = wm + mt * 16 + lr, cc = kb + lc;
        af[mt][0] = __float_as_uint(Ab[rb * 36 + cc]);
        af[mt][1] = __float_as_uint(Ab[(rb + 8) * 36 + cc]);
        af[mt][2] = __float_as_uint(Ab[rb * 36 + cc + 4]);
        af[mt][3] = __float_as_uint(Ab[(rb + 8) * 36 + cc + 4]);
      }
#pragma unroll
      for (int nt = 0; nt < 4; nt++) {
        int cb = wn + nt * 8 + lr, rr = kb + lc;
        bf[nt][0]  = f2tf(Bb[rr * 72 + cb]);
        bf[nt][1]  = f2tf(Bb[(rr + 4) * 72 + cb]);
        bf2[nt][0] = f2tf(Bb2[rr * 72 + cb]);
        bf2[nt][1] = f2tf(Bb2[(rr + 4) * 72 + cb]);
      }
#pragma unroll
      for (int mt = 0; mt < 4; mt++)
#pragma unroll
        for (int nt = 0; nt < 4; nt++) {
          mma_tf32(acc[mt][nt], af[mt], bf[nt]);
          mma_tf32(acc2[mt][nt], af[mt], bf2[nt]);
        }
    }
    __syncthreads();
  }

#pragma unroll
  for (int mt = 0; mt < 4; mt++) {
#pragma unroll
    for (int half = 0; half < 2; half++) {
      int ml = wm + mt * 16 + lr + half * 8;
      int mm = m0 + ml;
      if (mm < ne) {
        size_t rowb = (size_t)(off + mm) * N;
#pragma unroll
        for (int nt = 0; nt < 4; nt++) {
          int nn = n0 + wn + nt * 8 + 2 * lc;
          float g0 = acc[mt][nt][half * 2], g1 = acc[mt][nt][half * 2 + 1];
          C[rowb + nn]     = roundtf(g0 * acc2[mt][nt][half * 2] / (1.f + __expf(-g0)));
          C[rowb + nn + 1] = roundtf(g1 * acc2[mt][nt][half * 2 + 1] / (1.f + __expf(-g1)));
        }
      }
    }
  }
}

// ------- causal flash attention (champion): tf32 mma, Q-frags in regs, 2 CTAs/SM -------
__global__ void __launch_bounds__(128, 2) flash_tc(const float* __restrict__ Q,
                                                   const float* __restrict__ Kp,
                                                   const float* __restrict__ Vp,
                                                   float* __restrict__ O) {
  extern __shared__ float sm[];
  float* Ks = sm;
  float* Vs = sm + 64 * 132;
  const int qt = gridDim.x - 1 - blockIdx.x;
  const int head = blockIdx.y, kh = head >> 2;
  const int tid = threadIdx.x, lane = tid & 31, w = tid >> 5;
  const int q0 = qt * 64, lr = lane >> 2, lc = lane & 3;
  const int rloc = w * 16 + lr;
  const int gr0 = q0 + rloc, gr1 = gr0 + 8;

  for (int i = tid; i < 64 * 32; i += 128) {
    int r = i >> 5, c4 = (i & 31) << 2;
    *(float4*)&Ks[r * 132 + c4] = *(const float4*)&Q[(size_t)(q0 + r) * 2048 + head * HDIM + c4];
  }
  __syncthreads();
  uint32_t qf[16][4];
#pragma unroll
  for (int ks = 0; ks < 16; ks++) {
    const int kb = ks * 8;
    qf[ks][0] = __float_as_uint(Ks[rloc * 132 + kb + lc]);
    qf[ks][1] = __float_as_uint(Ks[(rloc + 8) * 132 + kb + lc]);
    qf[ks][2] = __float_as_uint(Ks[rloc * 132 + kb + lc + 4]);
    qf[ks][3] = __float_as_uint(Ks[(rloc + 8) * 132 + kb + lc + 4]);
  }

  float mr0 = -3.0e38f, mr1 = -3.0e38f, li0 = 0.f, li1 = 0.f;
  float oacc[16][4];
#pragma unroll
  for (int i = 0; i < 16; i++)
#pragma unroll
    for (int j = 0; j < 4; j++) oacc[i][j] = 0.f;

  for (int kt = 0; kt <= qt; kt++) {
    __syncthreads();
    for (int i = tid; i < 64 * 32; i += 128) {
      int r = i >> 5, c4 = (i & 31) << 2;
      size_t gb = (size_t)(kt * 64 + r) * 512 + kh * HDIM + c4;
      *(float4*)&Ks[r * 132 + c4] = *(const float4*)&Kp[gb];
      *(float4*)&Vs[r * 132 + c4] = *(const float4*)&Vp[gb];
    }
    __syncthreads();

    float sacc[8][4];
#pragma unroll
    for (int i = 0; i < 8; i++)
#pragma unroll
      for (int j = 0; j < 4; j++) sacc[i][j] = 0.f;
#pragma unroll
    for (int ks = 0; ks < 16; ks++) {
      const int kb = ks * 8;
#pragma unroll
      for (int nt = 0; nt < 8; nt++) {
        int cb = nt * 8 + lr;
        uint32_t b[2];
        b[0] = __float_as_uint(Ks[cb * 132 + kb + lc]);
        b[1] = __float_as_uint(Ks[cb * 132 + kb + lc + 4]);
        mma_tf32(sacc[nt], qf[ks], b);
      }
    }

    const bool diag = (kt == qt);
#pragma unroll
    for (int nt = 0; nt < 8; nt++) {
      int gc = kt * 64 + nt * 8 + 2 * lc;
#pragma unroll
      for (int j = 0; j < 4; j++) {
        float v = sacc[nt][j] * ATT_SCALE;
        if (diag && (gc + (j & 1)) > ((j < 2) ? gr0 : gr1)) v = -1.0e30f;
        sacc[nt][j] = v;
      }
    }

    float mx0 = -3.0e38f, mx1 = -3.0e38f;
#pragma unroll
    for (int nt = 0; nt < 8; nt++) {
      mx0 = fmaxf(mx0, fmaxf(sacc[nt][0], sacc[nt][1]));
      mx1 = fmaxf(mx1, fmaxf(sacc[nt][2], sacc[nt][3]));
    }
    mx0 = fmaxf(mx0, __shfl_xor_sync(0xffffffffu, mx0, 1));
    mx0 = fmaxf(mx0, __shfl_xor_sync(0xffffffffu, mx0, 2));
    mx1 = fmaxf(mx1, __shfl_xor_sync(0xffffffffu, mx1, 1));
    mx1 = fmaxf(mx1, __shfl_xor_sync(0xffffffffu, mx1, 2));
    float mn0 = fmaxf(mr0, mx0), mn1 = fmaxf(mr1, mx1);
    float co0 = __expf(mr0 - mn0), co1 = __expf(mr1 - mn1);
    mr0 = mn0; mr1 = mn1;
    float rs0 = 0.f, rs1 = 0.f;
#pragma unroll
    for (int nt = 0; nt < 8; nt++) {
      sacc[nt][0] = __expf(sacc[nt][0] - mn0);
      sacc[nt][1] = __expf(sacc[nt][1] - mn0);
      sacc[nt][2] = __expf(sacc[nt][2] - mn1);
      sacc[nt][3] = __expf(sacc[nt][3] - mn1);
      rs0 += sacc[nt][0] + sacc[nt][1];
      rs1 += sacc[nt][2] + sacc[nt][3];
    }
    rs0 += __shfl_xor_sync(0xffffffffu, rs0, 1);
    rs0 += __shfl_xor_sync(0xffffffffu, rs0, 2);
    rs1 += __shfl_xor_sync(0xffffffffu, rs1, 1);
    rs1 += __shfl_xor_sync(0xffffffffu, rs1, 2);
    li0 = li0 * co0 + rs0; li1 = li1 * co1 + rs1;
#pragma unroll
    for (int i = 0; i < 16; i++) {
      oacc[i][0] *= co0; oacc[i][1] *= co0;
      oacc[i][2] *= co1; oacc[i][3] *= co1;
    }

#pragma unroll
    for (int kc = 0; kc < 8; kc++) {
      int src0 = (lane & ~3) | (lc >> 1), src1 = src0 + 2;
      float v00 = __shfl_sync(0xffffffffu, sacc[kc][0], src0);
      float v01 = __shfl_sync(0xffffffffu, sacc[kc][1], src0);
      float v10 = __shfl_sync(0xffffffffu, sacc[kc][0], src1);
      float v11 = __shfl_sync(0xffffffffu, sacc[kc][1], src1);
      float w00 = __shfl_sync(0xffffffffu, sacc[kc][2], src0);
      float w01 = __shfl_sync(0xffffffffu, sacc[kc][3], src0);
      float w10 = __shfl_sync(0xffffffffu, sacc[kc][2], src1);
      float w11 = __shfl_sync(0xffffffffu, sacc[kc][3], src1);
      uint32_t a[4];
      a[0] = f2tf((lc & 1) ? v01 : v00);
      a[1] = f2tf((lc & 1) ? w01 : w00);
      a[2] = f2tf((lc & 1) ? v11 : v10);
      a[3] = f2tf((lc & 1) ? w11 : w10);
      const int kb = kc * 8;
#pragma unroll
      for (int nt = 0; nt < 16; nt++) {
        int cb = nt * 8 + lr;
        uint32_t b[2];
        b[0] = __float_as_uint(Vs[(kb + lc) * 132 + cb]);
        b[1] = __float_as_uint(Vs[(kb + lc + 4) * 132 + cb]);
        mma_tf32(oacc[nt], a, b);
      }
    }
  }

  float inv0 = 1.f / li0, inv1 = 1.f / li1;
  size_t r0b = (size_t)gr0 * 2048 + head * HDIM, r1b = (size_t)gr1 * 2048 + head * HDIM;
#pragma unroll
  for (int nt = 0; nt < 16; nt++) {
    int nn = nt * 8 + 2 * lc;
    O[r0b + nn]     = roundtf(oacc[nt][0] * inv0);
    O[r0b + nn + 1] = roundtf(oacc[nt][1] * inv0);
    O[r1b + nn]     = roundtf(oacc[nt][2] * inv1);
    O[r1b + nn + 1] = roundtf(oacc[nt][3] * inv1);
  }
}

// ---------------- routing ----------------
__global__ void routing_kernel() {
  __shared__ int scnt[NEXP];
  int tid = threadIdx.x;
  if (tid < NEXP) scnt[tid] = 0;
  __syncthreads();
  for (int s = tid; s < SEQ * 2; s += blockDim.x) {
    int e = g_topidx[s];
    int p = atomicAdd(&scnt[e], 1);
    g_pos[s] = p;
    g_tok[e * SEQ + p] = s >> 1;
  }
  __syncthreads();
  if (tid == 0) {
    int acc = 0;
    for (int e = 0; e < NEXP; e++) {
      g_off[e] = acc; g_cnt[e] = scnt[e]; acc += scnt[e];
    }
  }
}

// ---------------- MoE combine (float4) ----------------
__global__ void combine_kernel(float* __restrict__ out, const float* __restrict__ moeo) {
  int t = blockIdx.x;
  int s0 = g_off[g_topidx[t * 2]] + g_pos[t * 2];
  int s1 = g_off[g_topidx[t * 2 + 1]] + g_pos[t * 2 + 1];
  float w0 = g_topw[t * 2], w1 = g_topw[t * 2 + 1];
  const float4* r0 = (const float4*)(moeo + (size_t)s0 * HID);
  const float4* r1 = (const float4*)(moeo + (size_t)s1 * HID);
  float4* o = (float4*)(out + (size_t)t * HID);
  for (int i = threadIdx.x; i < HID / 4; i += blockDim.x) {
    float4 a = r0[i], b = r1[i], c = o[i];
    c.x += w0 * a.x + w1 * b.x;
    c.y += w0 * a.y + w1 * b.y;
    c.z += w0 * a.z + w1 * b.z;
    c.w += w0 * a.w + w1 * b.w;
    o[i] = c;
  }
}

// ---------------- launch ----------------
extern "C" void kernel_launch(void* const* d_in, const int* in_sizes, int n_in,
                              void* d_out, int out_size) {
  const float* hidden = (const float*)d_in[0];
  const float* cosp = (const float*)d_in[2];
  const float* sinp = (const float*)d_in[3];
  const float* ln1  = (const float*)d_in[4];
  const float* ln2  = (const float*)d_in[5];
  const float* wq   = (const float*)d_in[6];
  const float* wk   = (const float*)d_in[7];
  const float* wv   = (const float*)d_in[8];
  const float* wo   = (const float*)d_in[9];
  const float* qn   = (const float*)d_in[10];
  const float* kn   = (const float*)d_in[11];
  const float* gw   = (const float*)d_in[12];
  const float* be   = (const float*)d_in[13];
  const float* w1   = (const float*)d_in[14];
  const float* w3   = (const float*)d_in[15];
  const float* w2   = (const float*)d_in[16];
  float* out = (float*)d_out;

  float *x1, *q, *k, *v, *attn, *x3r, *moeh, *moeo;
  cudaGetSymbolAddress((void**)&x1, g_x1);
  cudaGetSymbolAddress((void**)&q, g_q);
  cudaGetSymbolAddress((void**)&k, g_k);
  cudaGetSymbolAddress((void**)&v, g_v);
  cudaGetSymbolAddress((void**)&attn, g_attn);
  cudaGetSymbolAddress((void**)&x3r, g_x3r);
  cudaGetSymbolAddress((void**)&moeh, g_moeh);
  cudaGetSymbolAddress((void**)&moeo, g_moeo);

  const int GS   = (2 * 128 * 36 + 2 * 32 * 136) * 4;  // 71680 B
  const int GS4D = (2 * 128 * 36 + 4 * 32 * 72) * 4;   // 73728 B
  cudaFuncSetAttribute(gemm4<1>, cudaFuncAttributeMaxDynamicSharedMemorySize, GS);
  cudaFuncSetAttribute(gemm4<4>, cudaFuncAttributeMaxDynamicSharedMemorySize, GS);
  cudaFuncSetAttribute(gemm4<5>, cudaFuncAttributeMaxDynamicSharedMemorySize, GS);
  cudaFuncSetAttribute(gemm4d, cudaFuncAttributeMaxDynamicSharedMemorySize, GS4D);
  const int FS = 2 * 64 * 132 * 4;                     // 67584 B -> 2 CTAs/SM
  cudaFuncSetAttribute(flash_tc, cudaFuncAttributeMaxDynamicSharedMemorySize, FS);

  rmsnorm_kernel<<<SEQ, 256>>>(hidden, ln1, x1, HID);                         // #1
  gemm4<5><<<dim3(16, 24), 128, GS>>>(x1, wq, nullptr, q, 2048, 2048, wk, wv, k, v); // #2
  rms_rope_qk<<<dim3(SEQ, 2), 256>>>(q, k, qn, kn, cosp, sinp);               // #3
  flash_tc<<<dim3(32, NHEADS), 128, FS>>>(q, k, v, attn);                     // #4 <- profiled
  gemm4<1><<<dim3(16, 16), 128, GS>>>(attn, wo, hidden, out, 2048, 2048,
                                      nullptr, nullptr, nullptr, nullptr);
  rmsnorm_gate<<<SEQ, 256>>>(out, ln2, x3r, gw, be);
  routing_kernel<<<1, 256>>>();
  gemm4d<<<dim3(16, 16, 8), 128, GS4D>>>(x3r, w1, w3, moeh, IDIM, HID);
  gemm4<4><<<dim3(16, 16, 8), 128, GS>>>(moeh, w2, nullptr, moeo, HID, IDIM,
                                         nullptr, nullptr, nullptr, nullptr);
  combine_kernel<<<SEQ, 256>>>(out, moeo);
}

// round 15
// speedup vs baseline: 1.0484x; 1.0255x over previous
#include <cuda_runtime.h>
#include <math.h>
#include <stdint.h>

#define SEQ   2048
#define HID   2048
#define NHEADS 16
#define NKVH   4
#define HDIM   128
#define NEXP   8
#define IDIM   1024
#define NSLOT (2 * SEQ)
#define ATT_SCALE 0.08838834764831845f

__device__ float g_x1[SEQ * HID];
__device__ float g_q[SEQ * NHEADS * HDIM];
__device__ float g_k[SEQ * NKVH * HDIM];
__device__ float g_v[SEQ * NKVH * HDIM];
__device__ float g_attn[SEQ * NHEADS * HDIM];
__device__ float g_x3r[SEQ * HID];
__device__ float g_moeh[NSLOT * IDIM];
__device__ float g_moeo[NSLOT * HID];
__device__ int   g_topidx[SEQ * 2];
__device__ float g_topw[SEQ * 2];
__device__ int   g_pos[SEQ * 2];
__device__ int   g_cnt[NEXP];
__device__ int   g_off[NEXP];
__device__ int   g_tok[NEXP * SEQ];

__device__ __forceinline__ uint32_t f2tf(float x) {
  uint32_t r; asm("cvt.rna.tf32.f32 %0, %1;" : "=r"(r) : "f"(x)); return r;
}
__device__ __forceinline__ float roundtf(float x) { return __uint_as_float(f2tf(x)); }

__device__ __forceinline__ void mma_tf32(float* c, const uint32_t* a, const uint32_t* b) {
  asm volatile(
      "mma.sync.aligned.m16n8k8.row.col.f32.tf32.tf32.f32 "
      "{%0,%1,%2,%3}, {%4,%5,%6,%7}, {%8,%9}, {%0,%1,%2,%3};"
      : "+f"(c[0]), "+f"(c[1]), "+f"(c[2]), "+f"(c[3])
      : "r"(a[0]), "r"(a[1]), "r"(a[2]), "r"(a[3]), "r"(b[0]), "r"(b[1]));
}
__device__ __forceinline__ void cpasync16(uint32_t dst, const float* src) {
  asm volatile("cp.async.cg.shared.global [%0], [%1], 16;\n" :: "r"(dst), "l"(src));
}
__device__ __forceinline__ void cpcommit() { asm volatile("cp.async.commit_group;\n"); }
template <int NN> __device__ __forceinline__ void cpwait() {
  asm volatile("cp.async.wait_group %0;\n" :: "n"(NN));
}

// ---------------- RMSNorm (tf32-rounded out) ----------------
__global__ void rmsnorm_kernel(const float* __restrict__ x, const float* __restrict__ w,
                               float* __restrict__ yr, int cols) {
  int row = blockIdx.x;
  const float* xr = x + (size_t)row * cols;
  float ss = 0.f;
  for (int i = threadIdx.x; i < cols; i += blockDim.x) { float v = xr[i]; ss += v * v; }
#pragma unroll
  for (int o = 16; o; o >>= 1) ss += __shfl_xor_sync(0xffffffffu, ss, o);
  __shared__ float sred[8]; __shared__ float sscale;
  if ((threadIdx.x & 31) == 0) sred[threadIdx.x >> 5] = ss;
  __syncthreads();
  if (threadIdx.x == 0) {
    float t = 0.f;
#pragma unroll
    for (int i = 0; i < 8; i++) t += sred[i];
    sscale = rsqrtf(t / (float)cols + 1e-6f);
  }
  __syncthreads();
  float sc = sscale;
  for (int i = threadIdx.x; i < cols; i += blockDim.x)
    yr[(size_t)row * cols + i] = roundtf(xr[i] * sc * w[i]);
}

// ------- fused ln2 RMSNorm + MoE gate (identical arithmetic order to split version) -----
__global__ void rmsnorm_gate(const float* __restrict__ x, const float* __restrict__ w,
                             float* __restrict__ yr, const float* __restrict__ GW,
                             const float* __restrict__ BE) {
  int row = blockIdx.x;
  const float* xr = x + (size_t)row * HID;
  float ss = 0.f;
  for (int i = threadIdx.x; i < HID; i += blockDim.x) { float v = xr[i]; ss += v * v; }
#pragma unroll
  for (int o = 16; o; o >>= 1) ss += __shfl_xor_sync(0xffffffffu, ss, o);
  __shared__ float sred[8]; __shared__ float sscale;
  if ((threadIdx.x & 31) == 0) sred[threadIdx.x >> 5] = ss;
  __syncthreads();
  if (threadIdx.x == 0) {
    float t = 0.f;
#pragma unroll
    for (int i = 0; i < 8; i++) t += sred[i];
    sscale = rsqrtf(t / (float)HID + 1e-6f);
  }
  __syncthreads();
  float sc = sscale;
  float gacc[NEXP];
#pragma unroll
  for (int e = 0; e < NEXP; e++) gacc[e] = 0.f;
  for (int i = threadIdx.x; i < HID; i += blockDim.x) {
    float v = xr[i] * sc * w[i];
    yr[(size_t)row * HID + i] = roundtf(v);
    const float* g = GW + (size_t)i * NEXP;
#pragma unroll
    for (int e = 0; e < NEXP; e++) gacc[e] += v * g[e];
  }
#pragma unroll
  for (int e = 0; e < NEXP; e++)
#pragma unroll
    for (int o = 16; o; o >>= 1) gacc[e] += __shfl_xor_sync(0xffffffffu, gacc[e], o);
  __shared__ float ws[8][NEXP];
  if ((threadIdx.x & 31) == 0)
#pragma unroll
    for (int e = 0; e < NEXP; e++) ws[threadIdx.x >> 5][e] = gacc[e];
  __syncthreads();
  if (threadIdx.x == 0) {
    float scv[NEXP], bi[NEXP];
#pragma unroll
    for (int e = 0; e < NEXP; e++) {
      float lg = 0.f;
#pragma unroll
      for (int wdx = 0; wdx < 8; wdx++) lg += ws[wdx][e];
      scv[e] = 1.f / (1.f + expf(-lg));
      bi[e] = scv[e] + BE[e];
    }
    int i0 = 0;
    for (int e = 1; e < NEXP; e++) if (bi[e] > bi[i0]) i0 = e;
    int i1 = -1;
    for (int e = 0; e < NEXP; e++) {
      if (e == i0) continue;
      if (i1 < 0 || bi[e] > bi[i1]) i1 = e;
    }
    float w0 = scv[i0], w1 = scv[i1];
    float ssum = fmaxf(w0 + w1, 1e-12f);
    g_topidx[row * 2] = i0; g_topidx[row * 2 + 1] = i1;
    g_topw[row * 2] = w0 / ssum; g_topw[row * 2 + 1] = w1 / ssum;
  }
}

// ------- fused rmsnorm + partial RoPE for Q (y=0) and K (y=1), in place, tf32 out -------
__global__ void rms_rope_qk(float* __restrict__ qx, float* __restrict__ kx,
                            const float* __restrict__ qw, const float* __restrict__ kw,
                            const float* __restrict__ cp, const float* __restrict__ sp) {
  const int s = blockIdx.x;
  const int nh = (blockIdx.y == 0) ? NHEADS : NKVH;
  float* xr = ((blockIdx.y == 0) ? qx : kx) + (size_t)s * nh * HDIM;
  const float* w = (blockIdx.y == 0) ? qw : kw;
  const int cols = nh * HDIM;
  float ss = 0.f;
  for (int i = threadIdx.x; i < cols; i += blockDim.x) { float v = xr[i]; ss += v * v; }
#pragma unroll
  for (int o = 16; o; o >>= 1) ss += __shfl_xor_sync(0xffffffffu, ss, o);
  __shared__ float sred[8]; __shared__ float sscale;
  if ((threadIdx.x & 31) == 0) sred[threadIdx.x >> 5] = ss;
  __syncthreads();
  if (threadIdx.x == 0) {
    float t = 0.f;
#pragma unroll
    for (int i = 0; i < 8; i++) t += sred[i];
    sscale = rsqrtf(t / (float)cols + 1e-6f);
  }
  __syncthreads();
  float sc = sscale;
  for (int i = threadIdx.x; i < nh * 64; i += blockDim.x) {
    int h = i >> 6, sl = i & 63;
    if (sl < 32) {
      int i0 = h * HDIM + sl, i1 = i0 + 32;
      float a = xr[i0] * sc * w[i0], b = xr[i1] * sc * w[i1];
      float c = cp[s * 64 + sl], sn = sp[s * 64 + sl];
      xr[i0] = roundtf(a * c - b * sn);
      xr[i1] = roundtf(b * c + a * sn);
    } else {
      int i0 = h * HDIM + 32 + sl, i1 = i0 + 32;
      xr[i0] = roundtf(xr[i0] * sc * w[i0]);
      xr[i1] = roundtf(xr[i1] * sc * w[i1]);
    }
  }
}

// ------- tf32 GEMM (champion): 4 warps, warp 64x64, CTA 128x128x32, 2-stage ------------
template <int MODE>
__global__ void __launch_bounds__(128, 2)
gemm4(const float* __restrict__ A, const float* __restrict__ B,
      const float* __restrict__ D, float* __restrict__ C, int N, int K,
      const float* __restrict__ B2, const float* __restrict__ B3,
      float* __restrict__ C2, float* __restrict__ C3) {
  extern __shared__ float smem[];
  const int tid = threadIdx.x, lane = tid & 31, wid = tid >> 5;
  const int lr = lane >> 2, lc = lane & 3;
  const int wm = (wid >> 1) * 64, wn = (wid & 1) * 64;
  const int m0 = blockIdx.x * 128, by = blockIdx.y;

  const float* Bp = B; int ldb = N; int n0 = by * 128;
  if (MODE == 5) {
    if (by < 16)      { Bp = B;  ldb = 2048; n0 = by * 128; }
    else if (by < 20) { Bp = B2; ldb = 512;  n0 = (by - 16) * 128; }
    else              { Bp = B3; ldb = 512;  n0 = (by - 20) * 128; }
  }

  int e = 0, ne = 0, off = 0;
  if (MODE == 4) {
    e = blockIdx.z; ne = g_cnt[e]; off = g_off[e];
    if (m0 >= ne) return;
    Bp += (size_t)e * (size_t)K * (size_t)ldb;
  }

  uint32_t aoff[8], boff[8], Adst[8], Bdst[8];
  uint32_t sbase = (uint32_t)__cvta_generic_to_shared(smem);
#pragma unroll
  for (int i = 0; i < 8; i++) {
    int cid = tid + i * 128;
    int r = cid >> 3, kc = (cid & 7) << 2;
    int row;
    if (MODE == 4) { int mm = m0 + r; if (mm >= ne) mm = ne - 1; row = off + mm; }
    else row = m0 + r;
    aoff[i] = (uint32_t)(row * K + kc);
    Adst[i] = sbase + (uint32_t)(r * 36 + kc) * 4u;
    int bk = cid >> 5, nc = (cid & 31) << 2;
    boff[i] = (uint32_t)(bk * ldb + n0 + nc);
    Bdst[i] = sbase + (uint32_t)(2 * 128 * 36 + bk * 136 + nc) * 4u;
  }
  const uint32_t stA = 128 * 36 * 4u, stB = 32 * 136 * 4u;
  const float* As = smem;
  const float* Bs = smem + 2 * 128 * 36;

  float acc[4][8][4];
#pragma unroll
  for (int a = 0; a < 4; a++)
#pragma unroll
    for (int b = 0; b < 8; b++)
#pragma unroll
      for (int c = 0; c < 4; c++) acc[a][b][c] = 0.f;

  const int nslab = K >> 5;
#pragma unroll
  for (int i = 0; i < 8; i++) {
    cpasync16(Adst[i], A + aoff[i]);
    cpasync16(Bdst[i], Bp + boff[i]);
  }
  cpcommit();

  for (int s = 0; s < nslab; s++) {
    if (s + 1 < nslab) {
      int kofs = (s + 1) << 5;
      uint32_t so = ((s + 1) & 1) ? 1u : 0u;
#pragma unroll
      for (int i = 0; i < 8; i++) {
        cpasync16(Adst[i] + so * stA, A + aoff[i] + kofs);
        cpasync16(Bdst[i] + so * stB, Bp + boff[i] + (size_t)kofs * ldb);
      }
      cpcommit();
      cpwait<1>();
    } else cpwait<0>();
    __syncthreads();

    const float* Ab = As + (s & 1) * (128 * 36);
    const float* Bb = Bs + (s & 1) * (32 * 136);
#pragma unroll
    for (int ks = 0; ks < 4; ks++) {
      const int kb = ks * 8;
      uint32_t af[4][4], bf[8][2];
#pragma unroll
      for (int mt = 0; mt < 4; mt++) {
        int rb = wm + mt * 16 + lr, cc = kb + lc;
        af[mt][0] = __float_as_uint(Ab[rb * 36 + cc]);
        af[mt][1] = __float_as_uint(Ab[(rb + 8) * 36 + cc]);
        af[mt][2] = __float_as_uint(Ab[rb * 36 + cc + 4]);
        af[mt][3] = __float_as_uint(Ab[(rb + 8) * 36 + cc + 4]);
      }
#pragma unroll
      for (int nt = 0; nt < 8; nt++) {
        int cb = wn + nt * 8 + lr, rr = kb + lc;
        bf[nt][0] = f2tf(Bb[rr * 136 + cb]);
        bf[nt][1] = f2tf(Bb[(rr + 4) * 136 + cb]);
      }
#pragma unroll
      for (int mt = 0; mt < 4; mt++)
#pragma unroll
        for (int nt = 0; nt < 8; nt++) mma_tf32(acc[mt][nt], af[mt], bf[nt]);
    }
    __syncthreads();
  }

  float* Cp = C; int ldc = N;
  if (MODE == 5) {
    if (by < 16)      { Cp = C;  ldc = 2048; }
    else if (by < 20) { Cp = C2; ldc = 512; }
    else              { Cp = C3; ldc = 512; }
  }
#pragma unroll
  for (int mt = 0; mt < 4; mt++) {
#pragma unroll
    for (int half = 0; half < 2; half++) {
      int ml = wm + mt * 16 + lr + half * 8;
      if (MODE == 1 || MODE == 5) {
        size_t rowb = (size_t)(m0 + ml) * ldc;
#pragma unroll
        for (int nt = 0; nt < 8; nt++) {
          int nn = n0 + wn + nt * 8 + 2 * lc;
          float v0 = acc[mt][nt][half * 2], v1 = acc[mt][nt][half * 2 + 1];
          if (MODE == 1) { v0 += D[rowb + nn]; v1 += D[rowb + nn + 1]; }
          if (MODE == 5 && by >= 20) { v0 = roundtf(v0); v1 = roundtf(v1); }
          Cp[rowb + nn] = v0; Cp[rowb + nn + 1] = v1;
        }
      } else {  // MODE 4
        int mm = m0 + ml;
        if (mm < ne) {
          size_t rowb = (size_t)(off + mm) * N;
#pragma unroll
          for (int nt = 0; nt < 8; nt++) {
            int nn = n0 + wn + nt * 8 + 2 * lc;
            C[rowb + nn]     = acc[mt][nt][half * 2];
            C[rowb + nn + 1] = acc[mt][nt][half * 2 + 1];
          }
        }
      }
    }
  }
}

// ------- fused MoE w1/w3 (champion): 4 warps, CTA 128x64, dual-B, 2-stage --------------
__global__ void __launch_bounds__(128, 2)
gemm4d(const float* __restrict__ A, const float* __restrict__ B,
       const float* __restrict__ B2, float* __restrict__ C, int N, int K) {
  extern __shared__ float smem[];
  __shared__ int toks[128];
  const int tid = threadIdx.x, lane = tid & 31, wid = tid >> 5;
  const int lr = lane >> 2, lc = lane & 3;
  const int wm = (wid >> 1) * 64, wn = (wid & 1) * 32;
  const int m0 = blockIdx.x * 128, n0 = blockIdx.y * 64;

  const int e = blockIdx.z;
  const int ne = g_cnt[e], off = g_off[e];
  if (m0 >= ne) return;
  const float* Bp  = B  + (size_t)e * (size_t)K * (size_t)N;
  const float* B2p = B2 + (size_t)e * (size_t)K * (size_t)N;
  {
    int mm = m0 + tid;
    toks[tid] = g_tok[e * SEQ + (mm < ne ? mm : ne - 1)];
  }
  __syncthreads();

  uint32_t aoff[8], boff[4], Adst[8], Bdst[4], B2dst[4];
  uint32_t sbase = (uint32_t)__cvta_generic_to_shared(smem);
#pragma unroll
  for (int i = 0; i < 8; i++) {
    int cid = tid + i * 128;
    int r = cid >> 3, kc = (cid & 7) << 2;
    aoff[i] = (uint32_t)(toks[r] * K + kc);
    Adst[i] = sbase + (uint32_t)(r * 36 + kc) * 4u;
  }
#pragma unroll
  for (int i = 0; i < 4; i++) {
    int cid = tid + i * 128;
    int bk = cid >> 4, nc = (cid & 15) << 2;
    boff[i] = (uint32_t)(bk * N + n0 + nc);
    Bdst[i]  = sbase + (uint32_t)(2 * 128 * 36 + bk * 72 + nc) * 4u;
    B2dst[i] = sbase + (uint32_t)(2 * 128 * 36 + 2 * 32 * 72 + bk * 72 + nc) * 4u;
  }
  const uint32_t stA = 128 * 36 * 4u, stB = 32 * 72 * 4u;
  const float* As  = smem;
  const float* Bs  = smem + 2 * 128 * 36;
  const float* Bs2 = smem + 2 * 128 * 36 + 2 * 32 * 72;

  float acc[4][4][4], acc2[4][4][4];
#pragma unroll
  for (int a = 0; a < 4; a++)
#pragma unroll
    for (int b = 0; b < 4; b++)
#pragma unroll
      for (int c = 0; c < 4; c++) { acc[a][b][c] = 0.f; acc2[a][b][c] = 0.f; }

  const int nslab = K >> 5;
#pragma unroll
  for (int i = 0; i < 8; i++) cpasync16(Adst[i], A + aoff[i]);
#pragma unroll
  for (int i = 0; i < 4; i++) {
    cpasync16(Bdst[i], Bp + boff[i]);
    cpasync16(B2dst[i], B2p + boff[i]);
  }
  cpcommit();

  for (int s = 0; s < nslab; s++) {
    if (s + 1 < nslab) {
      int kofs = (s + 1) << 5;
      uint32_t so = ((s + 1) & 1) ? 1u : 0u;
#pragma unroll
      for (int i = 0; i < 8; i++) cpasync16(Adst[i] + so * stA, A + aoff[i] + kofs);
#pragma unroll
      for (int i = 0; i < 4; i++) {
        cpasync16(Bdst[i] + so * stB, Bp + boff[i] + (size_t)kofs * N);
        cpasync16(B2dst[i] + so * stB, B2p + boff[i] + (size_t)kofs * N);
      }
      cpcommit();
      cpwait<1>();
    } else cpwait<0>();
    __syncthreads();

    const float* Ab  = As  + (s & 1) * (128 * 36);
    const float* Bb  = Bs  + (s & 1) * (32 * 72);
    const float* Bb2 = Bs2 + (s & 1) * (32 * 72);
#pragma unroll
    for (int ks = 0; ks < 4; ks++) {
      const int kb = ks * 8;
      uint32_t af[4][4], bf[4][2], bf2[4][2];
#pragma unroll
      for (int mt = 0; mt < 4; mt++) {
        int rb = wm + mt * 16 + lr, cc = kb + lc;
        af[mt][0] = __float_as_uint(Ab[rb * 36 + cc]);
        af[mt][1] = __float_as_uint(Ab[(rb + 8) * 36 + cc]);
        af[mt][2] = __float_as_uint(Ab[rb * 36 + cc + 4]);
        af[mt][3] = __float_as_uint(Ab[(rb + 8) * 36 + cc + 4]);
      }
#pragma unroll
      for (int nt = 0; nt < 4; nt++) {
        int cb = wn + nt * 8 + lr, rr = kb + lc;
        bf[nt][0]  = f2tf(Bb[rr * 72 + cb]);
        bf[nt][1]  = f2tf(Bb[(rr + 4) * 72 + cb]);
        bf2[nt][0] = f2tf(Bb2[rr * 72 + cb]);
        bf2[nt][1] = f2tf(Bb2[(rr + 4) * 72 + cb]);
      }
#pragma unroll
      for (int mt = 0; mt < 4; mt++)
#pragma unroll
        for (int nt = 0; nt < 4; nt++) {
          mma_tf32(acc[mt][nt], af[mt], bf[nt]);
          mma_tf32(acc2[mt][nt], af[mt], bf2[nt]);
        }
    }
    __syncthreads();
  }

#pragma unroll
  for (int mt = 0; mt < 4; mt++) {
#pragma unroll
    for (int half = 0; half < 2; half++) {
      int ml = wm + mt * 16 + lr + half * 8;
      int mm = m0 + ml;
      if (mm < ne) {
        size_t rowb = (size_t)(off + mm) * N;
#pragma unroll
        for (int nt = 0; nt < 4; nt++) {
          int nn = n0 + wn + nt * 8 + 2 * lc;
          float g0 = acc[mt][nt][half * 2], g1 = acc[mt][nt][half * 2 + 1];
          C[rowb + nn]     = roundtf(g0 * acc2[mt][nt][half * 2] / (1.f + __expf(-g0)));
          C[rowb + nn + 1] = roundtf(g1 * acc2[mt][nt][half * 2 + 1] / (1.f + __expf(-g1)));
        }
      }
    }
  }
}

// ------- causal flash attention: tf32 mma, Q-frags in regs, cp.async K/V staging -------
__global__ void __launch_bounds__(128, 2) flash_tc(const float* __restrict__ Q,
                                                   const float* __restrict__ Kp,
                                                   const float* __restrict__ Vp,
                                                   float* __restrict__ O) {
  extern __shared__ float sm[];
  float* Ks = sm;
  float* Vs = sm + 64 * 132;
  const int qt = gridDim.x - 1 - blockIdx.x;
  const int head = blockIdx.y, kh = head >> 2;
  const int tid = threadIdx.x, lane = tid & 31, w = tid >> 5;
  const int q0 = qt * 64, lr = lane >> 2, lc = lane & 3;
  const int rloc = w * 16 + lr;
  const int gr0 = q0 + rloc, gr1 = gr0 + 8;

  uint32_t sbase = (uint32_t)__cvta_generic_to_shared(sm);
  const uint32_t ksa = sbase, vsa = sbase + 64u * 132u * 4u;

  for (int i = tid; i < 64 * 32; i += 128) {
    int r = i >> 5, c4 = (i & 31) << 2;
    *(float4*)&Ks[r * 132 + c4] = *(const float4*)&Q[(size_t)(q0 + r) * 2048 + head * HDIM + c4];
  }
  __syncthreads();
  uint32_t qf[16][4];
#pragma unroll
  for (int ks = 0; ks < 16; ks++) {
    const int kb = ks * 8;
    qf[ks][0] = __float_as_uint(Ks[rloc * 132 + kb + lc]);
    qf[ks][1] = __float_as_uint(Ks[(rloc + 8) * 132 + kb + lc]);
    qf[ks][2] = __float_as_uint(Ks[rloc * 132 + kb + lc + 4]);
    qf[ks][3] = __float_as_uint(Ks[(rloc + 8) * 132 + kb + lc + 4]);
  }

  float mr0 = -3.0e38f, mr1 = -3.0e38f, li0 = 0.f, li1 = 0.f;
  float oacc[16][4];
#pragma unroll
  for (int i = 0; i < 16; i++)
#pragma unroll
    for (int j = 0; j < 4; j++) oacc[i][j] = 0.f;

  for (int kt = 0; kt <= qt; kt++) {
    __syncthreads();   // previous tile fully consumed
#pragma unroll
    for (int it = 0; it < 16; it++) {
      int i = tid + it * 128;
      int r = i >> 5, c4 = (i & 31) << 2;
      size_t gb = (size_t)(kt * 64 + r) * 512 + kh * HDIM + c4;
      uint32_t so = (uint32_t)(r * 132 + c4) * 4u;
      cpasync16(ksa + so, Kp + gb);
      cpasync16(vsa + so, Vp + gb);
    }
    cpcommit();
    cpwait<0>();
    __syncthreads();

    float sacc[8][4];
#pragma unroll
    for (int i = 0; i < 8; i++)
#pragma unroll
      for (int j = 0; j < 4; j++) sacc[i][j] = 0.f;
#pragma unroll
    for (int ks = 0; ks < 16; ks++) {
      const int kb = ks * 8;
#pragma unroll
      for (int nt = 0; nt < 8; nt++) {
        int cb = nt * 8 + lr;
        uint32_t b[2];
        b[0] = __float_as_uint(Ks[cb * 132 + kb + lc]);
        b[1] = __float_as_uint(Ks[cb * 132 + kb + lc + 4]);
        mma_tf32(sacc[nt], qf[ks], b);
      }
    }

    const bool diag = (kt == qt);
#pragma unroll
    for (int nt = 0; nt < 8; nt++) {
      int gc = kt * 64 + nt * 8 + 2 * lc;
#pragma unroll
      for (int j = 0; j < 4; j++) {
        float v = sacc[nt][j] * ATT_SCALE;
        if (diag && (gc + (j & 1)) > ((j < 2) ? gr0 : gr1)) v = -1.0e30f;
        sacc[nt][j] = v;
      }
    }

    float mx0 = -3.0e38f, mx1 = -3.0e38f;
#pragma unroll
    for (int nt = 0; nt < 8; nt++) {
      mx0 = fmaxf(mx0, fmaxf(sacc[nt][0], sacc[nt][1]));
      mx1 = fmaxf(mx1, fmaxf(sacc[nt][2], sacc[nt][3]));
    }
    mx0 = fmaxf(mx0, __shfl_xor_sync(0xffffffffu, mx0, 1));
    mx0 = fmaxf(mx0, __shfl_xor_sync(0xffffffffu, mx0, 2));
    mx1 = fmaxf(mx1, __shfl_xor_sync(0xffffffffu, mx1, 1));
    mx1 = fmaxf(mx1, __shfl_xor_sync(0xffffffffu, mx1, 2));
    float mn0 = fmaxf(mr0, mx0), mn1 = fmaxf(mr1, mx1);
    float co0 = __expf(mr0 - mn0), co1 = __expf(mr1 - mn1);
    mr0 = mn0; mr1 = mn1;
    float rs0 = 0.f, rs1 = 0.f;
#pragma unroll
    for (int nt = 0; nt < 8; nt++) {
      sacc[nt][0] = __expf(sacc[nt][0] - mn0);
      sacc[nt][1] = __expf(sacc[nt][1] - mn0);
      sacc[nt][2] = __expf(sacc[nt][2] - mn1);
      sacc[nt][3] = __expf(sacc[nt][3] - mn1);
      rs0 += sacc[nt][0] + sacc[nt][1];
      rs1 += sacc[nt][2] + sacc[nt][3];
    }
    rs0 += __shfl_xor_sync(0xffffffffu, rs0, 1);
    rs0 += __shfl_xor_sync(0xffffffffu, rs0, 2);
    rs1 += __shfl_xor_sync(0xffffffffu, rs1, 1);
    rs1 += __shfl_xor_sync(0xffffffffu, rs1, 2);
    li0 = li0 * co0 + rs0; li1 = li1 * co1 + rs1;
#pragma unroll
    for (int i = 0; i < 16; i++) {
      oacc[i][0] *= co0; oacc[i][1] *= co0;
      oacc[i][2] *= co1; oacc[i][3] *= co1;
    }

#pragma unroll
    for (int kc = 0; kc < 8; kc++) {
      int src0 = (lane & ~3) | (lc >> 1), src1 = src0 + 2;
      float v00 = __shfl_sync(0xffffffffu, sacc[kc][0], src0);
      float v01 = __shfl_sync(0xffffffffu, sacc[kc][1], src0);
      float v10 = __shfl_sync(0xffffffffu, sacc[kc][0], src1);
      float v11 = __shfl_sync(0xffffffffu, sacc[kc][1], src1);
      float w00 = __shfl_sync(0xffffffffu, sacc[kc][2], src0);
      float w01 = __shfl_sync(0xffffffffu, sacc[kc][3], src0);
      float w10 = __shfl_sync(0xffffffffu, sacc[kc][2], src1);
      float w11 = __shfl_sync(0xffffffffu, sacc[kc][3], src1);
      uint32_t a[4];
      a[0] = f2tf((lc & 1) ? v01 : v00);
      a[1] = f2tf((lc & 1) ? w01 : w00);
      a[2] = f2tf((lc & 1) ? v11 : v10);
      a[3] = f2tf((lc & 1) ? w11 : w10);
      const int kb = kc * 8;
#pragma unroll
      for (int nt = 0; nt < 16; nt++) {
        int cb = nt * 8 + lr;
        uint32_t b[2];
        b[0] = __float_as_uint(Vs[(kb + lc) * 132 + cb]);
        b[1] = __float_as_uint(Vs[(kb + lc + 4) * 132 + cb]);
        mma_tf32(oacc[nt], a, b);
      }
    }
  }

  float inv0 = 1.f / li0, inv1 = 1.f / li1;
  size_t r0b = (size_t)gr0 * 2048 + head * HDIM, r1b = (size_t)gr1 * 2048 + head * HDIM;
#pragma unroll
  for (int nt = 0; nt < 16; nt++) {
    int nn = nt * 8 + 2 * lc;
    O[r0b + nn]     = roundtf(oacc[nt][0] * inv0);
    O[r0b + nn + 1] = roundtf(oacc[nt][1] * inv0);
    O[r1b + nn]     = roundtf(oacc[nt][2] * inv1);
    O[r1b + nn + 1] = roundtf(oacc[nt][3] * inv1);
  }
}

// ---------------- routing ----------------
__global__ void routing_kernel() {
  __shared__ int scnt[NEXP];
  int tid = threadIdx.x;
  if (tid < NEXP) scnt[tid] = 0;
  __syncthreads();
  for (int s = tid; s < SEQ * 2; s += blockDim.x) {
    int e = g_topidx[s];
    int p = atomicAdd(&scnt[e], 1);
    g_pos[s] = p;
    g_tok[e * SEQ + p] = s >> 1;
  }
  __syncthreads();
  if (tid == 0) {
    int acc = 0;
    for (int e = 0; e < NEXP; e++) {
      g_off[e] = acc; g_cnt[e] = scnt[e]; acc += scnt[e];
    }
  }
}

// ---------------- MoE combine (float4) ----------------
__global__ void combine_kernel(float* __restrict__ out, const float* __restrict__ moeo) {
  int t = blockIdx.x;
  int s0 = g_off[g_topidx[t * 2]] + g_pos[t * 2];
  int s1 = g_off[g_topidx[t * 2 + 1]] + g_pos[t * 2 + 1];
  float w0 = g_topw[t * 2], w1 = g_topw[t * 2 + 1];
  const float4* r0 = (const float4*)(moeo + (size_t)s0 * HID);
  const float4* r1 = (const float4*)(moeo + (size_t)s1 * HID);
  float4* o = (float4*)(out + (size_t)t * HID);
  for (int i = threadIdx.x; i < HID / 4; i += blockDim.x) {
    float4 a = r0[i], b = r1[i], c = o[i];
    c.x += w0 * a.x + w1 * b.x;
    c.y += w0 * a.y + w1 * b.y;
    c.z += w0 * a.z + w1 * b.z;
    c.w += w0 * a.w + w1 * b.w;
    o[i] = c;
  }
}

// ---------------- launch ----------------
extern "C" void kernel_launch(void* const* d_in, const int* in_sizes, int n_in,
                              void* d_out, int out_size) {
  const float* hidden = (const float*)d_in[0];
  const float* cosp = (const float*)d_in[2];
  const float* sinp = (const float*)d_in[3];
  const float* ln1  = (const float*)d_in[4];
  const float* ln2  = (const float*)d_in[5];
  const float* wq   = (const float*)d_in[6];
  const float* wk   = (const float*)d_in[7];
  const float* wv   = (const float*)d_in[8];
  const float* wo   = (const float*)d_in[9];
  const float* qn   = (const float*)d_in[10];
  const float* kn   = (const float*)d_in[11];
  const float* gw   = (const float*)d_in[12];
  const float* be   = (const float*)d_in[13];
  const float* w1   = (const float*)d_in[14];
  const float* w3   = (const float*)d_in[15];
  const float* w2   = (const float*)d_in[16];
  float* out = (float*)d_out;

  float *x1, *q, *k, *v, *attn, *x3r, *moeh, *moeo;
  cudaGetSymbolAddress((void**)&x1, g_x1);
  cudaGetSymbolAddress((void**)&q, g_q);
  cudaGetSymbolAddress((void**)&k, g_k);
  cudaGetSymbolAddress((void**)&v, g_v);
  cudaGetSymbolAddress((void**)&attn, g_attn);
  cudaGetSymbolAddress((void**)&x3r, g_x3r);
  cudaGetSymbolAddress((void**)&moeh, g_moeh);
  cudaGetSymbolAddress((void**)&moeo, g_moeo);

  const int GS   = (2 * 128 * 36 + 2 * 32 * 136) * 4;  // 71680 B
  const int GS4D = (2 * 128 * 36 + 4 * 32 * 72) * 4;   // 73728 B
  cudaFuncSetAttribute(gemm4<1>, cudaFuncAttributeMaxDynamicSharedMemorySize, GS);
  cudaFuncSetAttribute(gemm4<4>, cudaFuncAttributeMaxDynamicSharedMemorySize, GS);
  cudaFuncSetAttribute(gemm4<5>, cudaFuncAttributeMaxDynamicSharedMemorySize, GS);
  cudaFuncSetAttribute(gemm4d, cudaFuncAttributeMaxDynamicSharedMemorySize, GS4D);
  const int FS = 2 * 64 * 132 * 4;                     // 67584 B -> 2 CTAs/SM
  cudaFuncSetAttribute(flash_tc, cudaFuncAttributeMaxDynamicSharedMemorySize, FS);

  rmsnorm_kernel<<<SEQ, 256>>>(hidden, ln1, x1, HID);                         // #1
  gemm4<5><<<dim3(16, 24), 128, GS>>>(x1, wq, nullptr, q, 2048, 2048, wk, wv, k, v); // #2
  rms_rope_qk<<<dim3(SEQ, 2), 256>>>(q, k, qn, kn, cosp, sinp);               // #3
  flash_tc<<<dim3(32, NHEADS), 128, FS>>>(q, k, v, attn);                     // #4 <- profiled
  gemm4<1><<<dim3(16, 16), 128, GS>>>(attn, wo, hidden, out, 2048, 2048,
                                      nullptr, nullptr, nullptr, nullptr);
  rmsnorm_gate<<<SEQ, 256>>>(out, ln2, x3r, gw, be);
  routing_kernel<<<1, 256>>>();
  gemm4d<<<dim3(16, 16, 8), 128, GS4D>>>(x3r, w1, w3, moeh, IDIM, HID);
  gemm4<4><<<dim3(16, 16, 8), 128, GS>>>(moeh, w2, nullptr, moeo, HID, IDIM,
                                         nullptr, nullptr, nullptr, nullptr);
  combine_kernel<<<SEQ, 256>>>(out, moeo);
}